// round 7
// baseline (speedup 1.0000x reference)
#include <cuda_runtime.h>
#include <cstdint>

#define HEADS 8
#define NSEQ  4096
#define FIN   512
#define HD    64
#define FOUT  512
#define NEG_INF -1e30f

// Scratch (allocation-free rule: __device__ globals)
__device__ float g_q[HEADS * NSEQ * HD];
__device__ float g_k[HEADS * NSEQ * HD];
__device__ float g_v[HEADS * NSEQ * HD];
__device__ float g_hcat[NSEQ * HEADS * HD];

__device__ __forceinline__ uint32_t f2tf(float f) {
    uint32_t r;
    asm("cvt.rna.tf32.f32 %0, %1;" : "=r"(r) : "f"(f));
    return r;
}

__device__ __forceinline__ void mma_tf32(float c[4],
    uint32_t a0, uint32_t a1, uint32_t a2, uint32_t a3,
    uint32_t b0, uint32_t b1)
{
    asm volatile(
        "mma.sync.aligned.m16n8k8.row.col.f32.tf32.tf32.f32 "
        "{%0,%1,%2,%3}, {%4,%5,%6,%7}, {%8,%9}, {%0,%1,%2,%3};"
        : "+f"(c[0]), "+f"(c[1]), "+f"(c[2]), "+f"(c[3])
        : "r"(a0), "r"(a1), "r"(a2), "r"(a3), "r"(b0), "r"(b1));
}

// ===========================================================================
// Shared TF32 NT-GEMM tile: C[128x64] = A[128x512] * B[64x512]^T.
// 256 threads, 8 warps (wm 0..3 x wn 0..1), warp tile 32x32.
// Pair-packed smem (pitch 72 == 8 mod 32): group-of-8 col j stored at
// (j&3)*2 + (j>>2), so each MMA operand pair (k+gc, k+gc+4) is one LDS.64.
// ===========================================================================
#define GP 72

__device__ __forceinline__ void gemm_tile_tf32(
    const float* __restrict__ A, const float* __restrict__ B,
    float* __restrict__ C, int ldC)
{
    extern __shared__ uint32_t smg[];
    uint32_t* As = smg;              // 128*GP
    uint32_t* Bs = smg + 128 * GP;   // 64*GP

    const int tid  = threadIdx.x;
    const int warp = tid >> 5;
    const int lane = tid & 31;
    const int wm   = warp >> 1;
    const int wn   = warp & 1;
    const int gr   = lane >> 2;
    const int gc   = lane & 3;

    float acc[2][4][4];
    #pragma unroll
    for (int i = 0; i < 2; i++)
        #pragma unroll
        for (int c = 0; c < 4; c++)
            #pragma unroll
            for (int j = 0; j < 4; j++) acc[i][c][j] = 0.0f;

    const int r    = tid >> 4;        // 0..15
    const int c4i  = tid & 15;        // float4 column index
    const int pb   = (c4i >> 1) * 8 + (c4i & 1);  // packed base within row

    for (int k0 = 0; k0 < FIN; k0 += 64) {
        #pragma unroll
        for (int rr = 0; rr < 8; rr++) {
            float4 v = *(const float4*)(A + (size_t)(r + rr * 16) * FIN + k0 + c4i * 4);
            uint32_t* p = As + (r + rr * 16) * GP + pb;
            p[0] = f2tf(v.x); p[2] = f2tf(v.y); p[4] = f2tf(v.z); p[6] = f2tf(v.w);
        }
        #pragma unroll
        for (int rr = 0; rr < 4; rr++) {
            float4 v = *(const float4*)(B + (size_t)(r + rr * 16) * FIN + k0 + c4i * 4);
            uint32_t* p = Bs + (r + rr * 16) * GP + pb;
            p[0] = f2tf(v.x); p[2] = f2tf(v.y); p[4] = f2tf(v.z); p[6] = f2tf(v.w);
        }
        __syncthreads();

        #pragma unroll
        for (int kk = 0; kk < 64; kk += 8) {
            uint2 a[2][2];
            #pragma unroll
            for (int i = 0; i < 2; i++) {
                a[i][0] = *(const uint2*)&As[(wm * 32 + i * 16 + gr) * GP + kk + 2 * gc];
                a[i][1] = *(const uint2*)&As[(wm * 32 + i * 16 + 8 + gr) * GP + kk + 2 * gc];
            }
            #pragma unroll
            for (int c = 0; c < 4; c++) {
                uint2 b = *(const uint2*)&Bs[(wn * 32 + c * 8 + gr) * GP + kk + 2 * gc];
                #pragma unroll
                for (int i = 0; i < 2; i++)
                    mma_tf32(acc[i][c], a[i][0].x, a[i][1].x, a[i][0].y, a[i][1].y, b.x, b.y);
            }
        }
        __syncthreads();
    }

    #pragma unroll
    for (int i = 0; i < 2; i++)
        #pragma unroll
        for (int c = 0; c < 4; c++) {
            const int row = wm * 32 + i * 16 + gr;
            const int col = wn * 32 + c * 8 + gc * 2;
            *(float2*)&C[(size_t)row * ldC + col]       = make_float2(acc[i][c][0], acc[i][c][1]);
            *(float2*)&C[(size_t)(row + 8) * ldC + col] = make_float2(acc[i][c][2], acc[i][c][3]);
        }
}

// Kernel 1: QKV projection via TF32 GEMM. grid = (32 row-tiles, 3 mats, 8 heads)
__global__ void __launch_bounds__(256) qkv_tf32_kernel(
    const float* __restrict__ X,
    const float* __restrict__ WQ,
    const float* __restrict__ WK,
    const float* __restrict__ WV)
{
    const int head  = blockIdx.z;
    const int which = blockIdx.y;
    const int m0    = blockIdx.x * 128;
    const float* A = X + (size_t)head * NSEQ * FIN + (size_t)m0 * FIN;
    const float* W = (which == 0 ? WQ : which == 1 ? WK : WV) + (size_t)head * HD * FIN;
    float* C = (which == 0 ? g_q : which == 1 ? g_k : g_v)
               + (size_t)head * NSEQ * HD + (size_t)m0 * HD;
    gemm_tile_tf32(A, W, C, HD);
}

// Kernel 3: output projection via TF32 GEMM. grid = (32 row-tiles, 8 col-tiles)
__global__ void __launch_bounds__(256) proj_tf32_kernel(
    const float* __restrict__ WO, float* __restrict__ out)
{
    const int m0 = blockIdx.x * 128;
    const int n0 = blockIdx.y * 64;
    const float* A = g_hcat + (size_t)m0 * (HEADS * HD);
    const float* B = WO + (size_t)n0 * (HEADS * HD);
    float* C = out + (size_t)m0 * FOUT + n0;
    gemm_tile_tf32(A, B, C, FOUT);
}

// ===========================================================================
// Kernel 2: flash-attention, TF32 MMA. Br=64, 8 warps, 2 blocks/SM.
// Q/K/P pair-packed (LDS.64 operands); V plain (row-split B pattern).
// K/V/mask LDGs hoisted above sync1 to overlap prev-iteration tail.
// ===========================================================================
__global__ void __launch_bounds__(256, 2) attn_kernel(const int* __restrict__ mask)
{
    extern __shared__ uint32_t sm[];
    uint32_t* Qs = sm;                       // 64*GP packed
    uint32_t* Ks = Qs + 64 * GP;             // 64*GP packed
    uint32_t* Ps = Ks + 64 * GP;             // 64*GP packed
    uint32_t* Vs = Ps + 64 * GP;             // 64*GP plain
    float* pmax = (float*)(Vs + 64 * GP);    // [2][64]
    float* psum = pmax + 128;                // [2][64]
    float* m_s  = psum + 128;                // [64]
    float* l_s  = m_s + 64;                  // [64]

    const int head = blockIdx.y;
    const int q0   = blockIdx.x * 64;
    const int tid  = threadIdx.x;
    const int warp = tid >> 5;
    const int lane = tid & 31;
    const int wm   = warp >> 1;              // 0..3
    const int wn   = warp & 1;               // 0..1
    const int gr   = lane >> 2;              // 0..7
    const int gc   = lane & 3;               // 0..3

    const float* Q = g_q + (size_t)head * NSEQ * HD;
    const float* K = g_k + (size_t)head * NSEQ * HD;
    const float* V = g_v + (size_t)head * NSEQ * HD;
    const int*   M = mask + (size_t)head * NSEQ * NSEQ;

    const int r   = tid >> 4;                // 0..15
    const int c4i = tid & 15;
    const int c4  = c4i * 4;
    const int pb  = (c4i >> 1) * 8 + (c4i & 1);
    // packed position of column gc*2 within its 8-group (pp+2 -> col gc*2+1)
    const int pp  = ((2 * gc) & 3) * 2 + (gc >> 1);

    // Load Q tile -> packed tf32 smem
    #pragma unroll
    for (int rr = 0; rr < 4; rr++) {
        float4 v = *(const float4*)(Q + (size_t)(q0 + r + rr * 16) * HD + c4);
        uint32_t* p = Qs + (r + rr * 16) * GP + pb;
        p[0] = f2tf(v.x); p[2] = f2tf(v.y); p[4] = f2tf(v.z); p[6] = f2tf(v.w);
    }
    if (tid < 64) { m_s[tid] = -3e38f; l_s[tid] = 0.0f; }

    float o[4][4];
    #pragma unroll
    for (int c = 0; c < 4; c++)
        #pragma unroll
        for (int j = 0; j < 4; j++) o[c][j] = 0.0f;

    const int r0 = wm * 16 + gr;
    const int r1 = r0 + 8;

    for (int kt = 0; kt < NSEQ / 64; kt++) {
        const int k0 = kt * 64;

        // Issue gmem loads BEFORE sync1 (overlap prev-iter PV of other warps)
        float4 kreg[4], vreg[4];
        #pragma unroll
        for (int rr = 0; rr < 4; rr++) {
            kreg[rr] = *(const float4*)(K + (size_t)(k0 + r + rr * 16) * HD + c4);
            vreg[rr] = *(const float4*)(V + (size_t)(k0 + r + rr * 16) * HD + c4);
        }
        int2 mk[4][2];
        #pragma unroll
        for (int c = 0; c < 4; c++) {
            const int col = k0 + wn * 32 + c * 8 + gc * 2;
            mk[c][0] = *(const int2*)(M + (size_t)(q0 + r0) * NSEQ + col);
            mk[c][1] = *(const int2*)(M + (size_t)(q0 + r1) * NSEQ + col);
        }
        __syncthreads();  // sync1: prev iteration fully consumed

        #pragma unroll
        for (int rr = 0; rr < 4; rr++) {
            uint32_t* pk = Ks + (r + rr * 16) * GP + pb;
            pk[0] = f2tf(kreg[rr].x); pk[2] = f2tf(kreg[rr].y);
            pk[4] = f2tf(kreg[rr].z); pk[6] = f2tf(kreg[rr].w);
            uint32_t* pv = Vs + (r + rr * 16) * GP + c4;   // plain layout
            pv[0] = f2tf(vreg[rr].x); pv[1] = f2tf(vreg[rr].y);
            pv[2] = f2tf(vreg[rr].z); pv[3] = f2tf(vreg[rr].w);
        }
        __syncthreads();  // sync2: tiles ready

        // ---- S = Q K^T ----
        float sc[4][4];
        #pragma unroll
        for (int c = 0; c < 4; c++)
            #pragma unroll
            for (int j = 0; j < 4; j++) sc[c][j] = 0.0f;

        #pragma unroll
        for (int kk = 0; kk < 64; kk += 8) {
            const uint2 aA = *(const uint2*)&Qs[r0 * GP + kk + 2 * gc];  // a0,a2
            const uint2 aB = *(const uint2*)&Qs[r1 * GP + kk + 2 * gc];  // a1,a3
            #pragma unroll
            for (int c = 0; c < 4; c++) {
                const uint2 b = *(const uint2*)&Ks[(wn * 32 + c * 8 + gr) * GP + kk + 2 * gc];
                mma_tf32(sc[c], aA.x, aB.x, aA.y, aB.y, b.x, b.y);
            }
        }

        // ---- scale + mask ----
        #pragma unroll
        for (int c = 0; c < 4; c++) {
            sc[c][0] = mk[c][0].x ? sc[c][0] * 0.125f : NEG_INF;
            sc[c][1] = mk[c][0].y ? sc[c][1] * 0.125f : NEG_INF;
            sc[c][2] = mk[c][1].x ? sc[c][2] * 0.125f : NEG_INF;
            sc[c][3] = mk[c][1].y ? sc[c][3] * 0.125f : NEG_INF;
        }

        // ---- partial row max ----
        float rm0 = -3e38f, rm1 = -3e38f;
        #pragma unroll
        for (int c = 0; c < 4; c++) {
            rm0 = fmaxf(rm0, fmaxf(sc[c][0], sc[c][1]));
            rm1 = fmaxf(rm1, fmaxf(sc[c][2], sc[c][3]));
        }
        rm0 = fmaxf(rm0, __shfl_xor_sync(0xFFFFFFFFu, rm0, 1));
        rm0 = fmaxf(rm0, __shfl_xor_sync(0xFFFFFFFFu, rm0, 2));
        rm1 = fmaxf(rm1, __shfl_xor_sync(0xFFFFFFFFu, rm1, 1));
        rm1 = fmaxf(rm1, __shfl_xor_sync(0xFFFFFFFFu, rm1, 2));
        if (gc == 0) { pmax[wn * 64 + r0] = rm0; pmax[wn * 64 + r1] = rm1; }
        __syncthreads();  // sync3: pmax visible

        const float mo0 = m_s[r0], mo1 = m_s[r1];
        const float mn0 = fmaxf(mo0, fmaxf(pmax[r0], pmax[64 + r0]));
        const float mn1 = fmaxf(mo1, fmaxf(pmax[r1], pmax[64 + r1]));

        // ---- exp, partial sums, P -> packed smem ----
        float rs0 = 0.0f, rs1 = 0.0f;
        #pragma unroll
        for (int c = 0; c < 4; c++) {
            sc[c][0] = __expf(sc[c][0] - mn0);
            sc[c][1] = __expf(sc[c][1] - mn0);
            sc[c][2] = __expf(sc[c][2] - mn1);
            sc[c][3] = __expf(sc[c][3] - mn1);
            rs0 += sc[c][0] + sc[c][1];
            rs1 += sc[c][2] + sc[c][3];
            const int gbase = (wn * 4 + c) * 8;
            Ps[r0 * GP + gbase + pp]     = f2tf(sc[c][0]);
            Ps[r0 * GP + gbase + pp + 2] = f2tf(sc[c][1]);
            Ps[r1 * GP + gbase + pp]     = f2tf(sc[c][2]);
            Ps[r1 * GP + gbase + pp + 2] = f2tf(sc[c][3]);
        }
        rs0 += __shfl_xor_sync(0xFFFFFFFFu, rs0, 1);
        rs0 += __shfl_xor_sync(0xFFFFFFFFu, rs0, 2);
        rs1 += __shfl_xor_sync(0xFFFFFFFFu, rs1, 1);
        rs1 += __shfl_xor_sync(0xFFFFFFFFu, rs1, 2);
        if (gc == 0) { psum[wn * 64 + r0] = rs0; psum[wn * 64 + r1] = rs1; }

        const float al0 = __expf(mo0 - mn0);
        const float al1 = __expf(mo1 - mn1);
        __syncthreads();  // sync4: Ps + psum visible

        // ---- O rescale + O += P V ----
        #pragma unroll
        for (int c = 0; c < 4; c++) {
            o[c][0] *= al0; o[c][1] *= al0;
            o[c][2] *= al1; o[c][3] *= al1;
        }
        #pragma unroll
        for (int kk = 0; kk < 64; kk += 8) {
            const uint2 aA = *(const uint2*)&Ps[r0 * GP + kk + 2 * gc];
            const uint2 aB = *(const uint2*)&Ps[r1 * GP + kk + 2 * gc];
            #pragma unroll
            for (int c = 0; c < 4; c++) {
                const int d = wn * 32 + c * 8 + gr;
                const uint32_t b0 = Vs[(kk + gc) * GP + d];
                const uint32_t b1 = Vs[(kk + gc + 4) * GP + d];
                mma_tf32(o[c], aA.x, aB.x, aA.y, aB.y, b0, b1);
            }
        }

        // ---- m/l update ----
        if (wn == 0 && lane < 16) {
            const int rw = wm * 16 + lane;
            const float mo = m_s[rw];
            const float mn = fmaxf(mo, fmaxf(pmax[rw], pmax[64 + rw]));
            l_s[rw] = l_s[rw] * __expf(mo - mn) + psum[rw] + psum[64 + rw];
            m_s[rw] = mn;
        }
    }
    __syncthreads();

    const float inv0 = 1.0f / l_s[r0];
    const float inv1 = 1.0f / l_s[r1];
    #pragma unroll
    for (int c = 0; c < 4; c++) {
        const int d = head * HD + wn * 32 + c * 8 + gc * 2;
        *(float2*)(g_hcat + (size_t)(q0 + r0) * (HEADS * HD) + d) =
            make_float2(o[c][0] * inv0, o[c][1] * inv0);
        *(float2*)(g_hcat + (size_t)(q0 + r1) * (HEADS * HD) + d) =
            make_float2(o[c][2] * inv1, o[c][3] * inv1);
    }
}

// ---------------------------------------------------------------------------
extern "C" void kernel_launch(void* const* d_in, const int* in_sizes, int n_in,
                              void* d_out, int out_size)
{
    const float* X    = (const float*)d_in[0];
    const int*   mask = (const int*)  d_in[1];
    const float* WQ   = (const float*)d_in[2];
    const float* WK   = (const float*)d_in[3];
    const float* WV   = (const float*)d_in[4];
    const float* WO   = (const float*)d_in[5];
    float* out = (float*)d_out;

    const int gemm_smem = (128 + 64) * GP * 4;           // 55296 B
    const int attn_smem = 4 * 64 * GP * 4 + 384 * 4;     // 75264 B

    static int configured = 0;
    if (!configured) {
        cudaFuncSetAttribute(qkv_tf32_kernel,  cudaFuncAttributeMaxDynamicSharedMemorySize, gemm_smem);
        cudaFuncSetAttribute(proj_tf32_kernel, cudaFuncAttributeMaxDynamicSharedMemorySize, gemm_smem);
        cudaFuncSetAttribute(attn_kernel,      cudaFuncAttributeMaxDynamicSharedMemorySize, attn_smem);
        configured = 1;
    }

    qkv_tf32_kernel<<<dim3(NSEQ / 128, 3, HEADS), 256, gemm_smem>>>(X, WQ, WK, WV);
    attn_kernel<<<dim3(NSEQ / 64, HEADS), 256, attn_smem>>>(mask);
    proj_tf32_kernel<<<dim3(NSEQ / 128, FOUT / 64), 256, gemm_smem>>>(WO, out);
}

// round 9
// speedup vs baseline: 1.4126x; 1.4126x over previous
#include <cuda_runtime.h>
#include <cstdint>

#define HEADS 8
#define NSEQ  4096
#define FIN   512
#define HD    64
#define FOUT  512
#define NEG_INF -1e30f

// Scratch (allocation-free rule: __device__ globals)
__device__ float g_q[HEADS * NSEQ * HD];
__device__ float g_k[HEADS * NSEQ * HD];
__device__ float g_v[HEADS * NSEQ * HD];
__device__ float g_hcat[NSEQ * HEADS * HD];

__device__ __forceinline__ uint32_t f2tf(float f) {
    uint32_t r;
    asm("cvt.rna.tf32.f32 %0, %1;" : "=r"(r) : "f"(f));
    return r;
}

__device__ __forceinline__ void mma_tf32(float c[4],
    uint32_t a0, uint32_t a1, uint32_t a2, uint32_t a3,
    uint32_t b0, uint32_t b1)
{
    asm volatile(
        "mma.sync.aligned.m16n8k8.row.col.f32.tf32.tf32.f32 "
        "{%0,%1,%2,%3}, {%4,%5,%6,%7}, {%8,%9}, {%0,%1,%2,%3};"
        : "+f"(c[0]), "+f"(c[1]), "+f"(c[2]), "+f"(c[3])
        : "r"(a0), "r"(a1), "r"(a2), "r"(a3), "r"(b0), "r"(b1));
}

// ===========================================================================
// Shared TF32 NT-GEMM tile: C[128x64] = A[128x512] * B[64x512]^T.
// Pair-packed smem (pitch 72): group-of-8 col j at (j&3)*2 + (j>>2) ->
// each MMA operand pair (k+gc, k+gc+4) is one conflict-free LDS.64.
// ===========================================================================
#define GP 72

__device__ __forceinline__ void gemm_tile_tf32(
    const float* __restrict__ A, const float* __restrict__ B,
    float* __restrict__ C, int ldC)
{
    extern __shared__ uint32_t smg[];
    uint32_t* As = smg;              // 128*GP
    uint32_t* Bs = smg + 128 * GP;   // 64*GP

    const int tid  = threadIdx.x;
    const int warp = tid >> 5;
    const int lane = tid & 31;
    const int wm   = warp >> 1;
    const int wn   = warp & 1;
    const int gr   = lane >> 2;
    const int gc   = lane & 3;

    float acc[2][4][4];
    #pragma unroll
    for (int i = 0; i < 2; i++)
        #pragma unroll
        for (int c = 0; c < 4; c++)
            #pragma unroll
            for (int j = 0; j < 4; j++) acc[i][c][j] = 0.0f;

    const int r    = tid >> 4;        // 0..15
    const int c4i  = tid & 15;        // float4 column index
    const int pb   = (c4i >> 1) * 8 + (c4i & 1);  // packed base within row

    for (int k0 = 0; k0 < FIN; k0 += 64) {
        #pragma unroll
        for (int rr = 0; rr < 8; rr++) {
            float4 v = *(const float4*)(A + (size_t)(r + rr * 16) * FIN + k0 + c4i * 4);
            uint32_t* p = As + (r + rr * 16) * GP + pb;
            p[0] = f2tf(v.x); p[2] = f2tf(v.y); p[4] = f2tf(v.z); p[6] = f2tf(v.w);
        }
        #pragma unroll
        for (int rr = 0; rr < 4; rr++) {
            float4 v = *(const float4*)(B + (size_t)(r + rr * 16) * FIN + k0 + c4i * 4);
            uint32_t* p = Bs + (r + rr * 16) * GP + pb;
            p[0] = f2tf(v.x); p[2] = f2tf(v.y); p[4] = f2tf(v.z); p[6] = f2tf(v.w);
        }
        __syncthreads();

        #pragma unroll
        for (int kk = 0; kk < 64; kk += 8) {
            uint2 a[2][2];
            #pragma unroll
            for (int i = 0; i < 2; i++) {
                a[i][0] = *(const uint2*)&As[(wm * 32 + i * 16 + gr) * GP + kk + 2 * gc];
                a[i][1] = *(const uint2*)&As[(wm * 32 + i * 16 + 8 + gr) * GP + kk + 2 * gc];
            }
            #pragma unroll
            for (int c = 0; c < 4; c++) {
                uint2 b = *(const uint2*)&Bs[(wn * 32 + c * 8 + gr) * GP + kk + 2 * gc];
                #pragma unroll
                for (int i = 0; i < 2; i++)
                    mma_tf32(acc[i][c], a[i][0].x, a[i][1].x, a[i][0].y, a[i][1].y, b.x, b.y);
            }
        }
        __syncthreads();
    }

    #pragma unroll
    for (int i = 0; i < 2; i++)
        #pragma unroll
        for (int c = 0; c < 4; c++) {
            const int row = wm * 32 + i * 16 + gr;
            const int col = wn * 32 + c * 8 + gc * 2;
            *(float2*)&C[(size_t)row * ldC + col]       = make_float2(acc[i][c][0], acc[i][c][1]);
            *(float2*)&C[(size_t)(row + 8) * ldC + col] = make_float2(acc[i][c][2], acc[i][c][3]);
        }
}

// Kernel 1: QKV projection via TF32 GEMM. grid = (32 row-tiles, 3 mats, 8 heads)
__global__ void __launch_bounds__(256) qkv_tf32_kernel(
    const float* __restrict__ X,
    const float* __restrict__ WQ,
    const float* __restrict__ WK,
    const float* __restrict__ WV)
{
    const int head  = blockIdx.z;
    const int which = blockIdx.y;
    const int m0    = blockIdx.x * 128;
    const float* A = X + (size_t)head * NSEQ * FIN + (size_t)m0 * FIN;
    const float* W = (which == 0 ? WQ : which == 1 ? WK : WV) + (size_t)head * HD * FIN;
    float* C = (which == 0 ? g_q : which == 1 ? g_k : g_v)
               + (size_t)head * NSEQ * HD + (size_t)m0 * HD;
    gemm_tile_tf32(A, W, C, HD);
}

// Kernel 3: output projection via TF32 GEMM. grid = (32 row-tiles, 8 col-tiles)
__global__ void __launch_bounds__(256) proj_tf32_kernel(
    const float* __restrict__ WO, float* __restrict__ out)
{
    const int m0 = blockIdx.x * 128;
    const int n0 = blockIdx.y * 64;
    const float* A = g_hcat + (size_t)m0 * (HEADS * HD);
    const float* B = WO + (size_t)n0 * (HEADS * HD);
    float* C = out + (size_t)m0 * FOUT + n0;
    gemm_tile_tf32(A, B, C, FOUT);
}

// ===========================================================================
// Kernel 2: flash-attention, TF32 MMA — R4 structure (loads AFTER sync1,
// no occupancy forcing) with pair-packed Q/K/P (one LDS.64 per operand pair).
// V plain layout (its B-fragment access is already row-split, conflict-free).
// ===========================================================================
__global__ void __launch_bounds__(256) attn_kernel(const int* __restrict__ mask)
{
    extern __shared__ uint32_t sm[];
    uint32_t* Qs = sm;                       // 64*GP packed
    uint32_t* Ks = Qs + 64 * GP;             // 64*GP packed
    uint32_t* Ps = Ks + 64 * GP;             // 64*GP packed
    uint32_t* Vs = Ps + 64 * GP;             // 64*GP plain
    float* pmax = (float*)(Vs + 64 * GP);    // [2][64]
    float* psum = pmax + 128;                // [2][64]
    float* m_s  = psum + 128;                // [64]
    float* l_s  = m_s + 64;                  // [64]

    const int head = blockIdx.y;
    const int q0   = blockIdx.x * 64;
    const int tid  = threadIdx.x;
    const int warp = tid >> 5;
    const int lane = tid & 31;
    const int wm   = warp >> 1;              // 0..3
    const int wn   = warp & 1;               // 0..1
    const int gr   = lane >> 2;              // 0..7
    const int gc   = lane & 3;               // 0..3

    const float* Q = g_q + (size_t)head * NSEQ * HD;
    const float* K = g_k + (size_t)head * NSEQ * HD;
    const float* V = g_v + (size_t)head * NSEQ * HD;
    const int*   M = mask + (size_t)head * NSEQ * NSEQ;

    const int r   = tid >> 4;                // 0..15
    const int c4i = tid & 15;
    const int c4  = c4i * 4;
    const int pb  = (c4i >> 1) * 8 + (c4i & 1);
    // packed position of col gc*2 within its 8-group (pp+2 -> col gc*2+1)
    const int pp  = ((2 * gc) & 3) * 2 + (gc >> 1);

    // Load Q tile -> packed tf32 smem
    #pragma unroll
    for (int rr = 0; rr < 4; rr++) {
        float4 v = *(const float4*)(Q + (size_t)(q0 + r + rr * 16) * HD + c4);
        uint32_t* p = Qs + (r + rr * 16) * GP + pb;
        p[0] = f2tf(v.x); p[2] = f2tf(v.y); p[4] = f2tf(v.z); p[6] = f2tf(v.w);
    }
    if (tid < 64) { m_s[tid] = -3e38f; l_s[tid] = 0.0f; }

    float o[4][4];
    #pragma unroll
    for (int c = 0; c < 4; c++)
        #pragma unroll
        for (int j = 0; j < 4; j++) o[c][j] = 0.0f;

    const int r0 = wm * 16 + gr;
    const int r1 = r0 + 8;

    for (int kt = 0; kt < NSEQ / 64; kt++) {
        const int k0 = kt * 64;
        __syncthreads();  // sync1: previous iteration fully consumed

        // Load K & V tiles (load+convert+store, no long register hoisting)
        #pragma unroll
        for (int rr = 0; rr < 4; rr++) {
            float4 kv = *(const float4*)(K + (size_t)(k0 + r + rr * 16) * HD + c4);
            float4 vv = *(const float4*)(V + (size_t)(k0 + r + rr * 16) * HD + c4);
            uint32_t* pk = Ks + (r + rr * 16) * GP + pb;
            pk[0] = f2tf(kv.x); pk[2] = f2tf(kv.y); pk[4] = f2tf(kv.z); pk[6] = f2tf(kv.w);
            uint32_t* pv = Vs + (r + rr * 16) * GP + c4;   // plain layout
            pv[0] = f2tf(vv.x); pv[1] = f2tf(vv.y); pv[2] = f2tf(vv.z); pv[3] = f2tf(vv.w);
        }
        // Prefetch mask fragments (C-fragment coords); hides under S-MMA
        int2 mk[4][2];
        #pragma unroll
        for (int c = 0; c < 4; c++) {
            const int col = k0 + wn * 32 + c * 8 + gc * 2;
            mk[c][0] = *(const int2*)(M + (size_t)(q0 + r0) * NSEQ + col);
            mk[c][1] = *(const int2*)(M + (size_t)(q0 + r1) * NSEQ + col);
        }
        __syncthreads();  // sync2: tiles ready

        // ---- S = Q K^T ----
        float sc[4][4];
        #pragma unroll
        for (int c = 0; c < 4; c++)
            #pragma unroll
            for (int j = 0; j < 4; j++) sc[c][j] = 0.0f;

        #pragma unroll
        for (int kk = 0; kk < 64; kk += 8) {
            const uint2 aA = *(const uint2*)&Qs[r0 * GP + kk + 2 * gc];  // a0,a2
            const uint2 aB = *(const uint2*)&Qs[r1 * GP + kk + 2 * gc];  // a1,a3
            #pragma unroll
            for (int c = 0; c < 4; c++) {
                const uint2 b = *(const uint2*)&Ks[(wn * 32 + c * 8 + gr) * GP + kk + 2 * gc];
                mma_tf32(sc[c], aA.x, aB.x, aA.y, aB.y, b.x, b.y);
            }
        }

        // ---- scale + mask ----
        #pragma unroll
        for (int c = 0; c < 4; c++) {
            sc[c][0] = mk[c][0].x ? sc[c][0] * 0.125f : NEG_INF;
            sc[c][1] = mk[c][0].y ? sc[c][1] * 0.125f : NEG_INF;
            sc[c][2] = mk[c][1].x ? sc[c][2] * 0.125f : NEG_INF;
            sc[c][3] = mk[c][1].y ? sc[c][3] * 0.125f : NEG_INF;
        }

        // ---- partial row max ----
        float rm0 = -3e38f, rm1 = -3e38f;
        #pragma unroll
        for (int c = 0; c < 4; c++) {
            rm0 = fmaxf(rm0, fmaxf(sc[c][0], sc[c][1]));
            rm1 = fmaxf(rm1, fmaxf(sc[c][2], sc[c][3]));
        }
        rm0 = fmaxf(rm0, __shfl_xor_sync(0xFFFFFFFFu, rm0, 1));
        rm0 = fmaxf(rm0, __shfl_xor_sync(0xFFFFFFFFu, rm0, 2));
        rm1 = fmaxf(rm1, __shfl_xor_sync(0xFFFFFFFFu, rm1, 1));
        rm1 = fmaxf(rm1, __shfl_xor_sync(0xFFFFFFFFu, rm1, 2));
        if (gc == 0) { pmax[wn * 64 + r0] = rm0; pmax[wn * 64 + r1] = rm1; }
        __syncthreads();  // sync3: pmax visible

        const float mo0 = m_s[r0], mo1 = m_s[r1];
        const float mn0 = fmaxf(mo0, fmaxf(pmax[r0], pmax[64 + r0]));
        const float mn1 = fmaxf(mo1, fmaxf(pmax[r1], pmax[64 + r1]));

        // ---- exp, partial sums, P -> packed smem ----
        float rs0 = 0.0f, rs1 = 0.0f;
        #pragma unroll
        for (int c = 0; c < 4; c++) {
            sc[c][0] = __expf(sc[c][0] - mn0);
            sc[c][1] = __expf(sc[c][1] - mn0);
            sc[c][2] = __expf(sc[c][2] - mn1);
            sc[c][3] = __expf(sc[c][3] - mn1);
            rs0 += sc[c][0] + sc[c][1];
            rs1 += sc[c][2] + sc[c][3];
            const int gbase = (wn * 4 + c) * 8;
            Ps[r0 * GP + gbase + pp]     = f2tf(sc[c][0]);
            Ps[r0 * GP + gbase + pp + 2] = f2tf(sc[c][1]);
            Ps[r1 * GP + gbase + pp]     = f2tf(sc[c][2]);
            Ps[r1 * GP + gbase + pp + 2] = f2tf(sc[c][3]);
        }
        rs0 += __shfl_xor_sync(0xFFFFFFFFu, rs0, 1);
        rs0 += __shfl_xor_sync(0xFFFFFFFFu, rs0, 2);
        rs1 += __shfl_xor_sync(0xFFFFFFFFu, rs1, 1);
        rs1 += __shfl_xor_sync(0xFFFFFFFFu, rs1, 2);
        if (gc == 0) { psum[wn * 64 + r0] = rs0; psum[wn * 64 + r1] = rs1; }

        const float al0 = __expf(mo0 - mn0);
        const float al1 = __expf(mo1 - mn1);
        __syncthreads();  // sync4: Ps + psum visible

        // ---- O rescale + O += P V ----
        #pragma unroll
        for (int c = 0; c < 4; c++) {
            o[c][0] *= al0; o[c][1] *= al0;
            o[c][2] *= al1; o[c][3] *= al1;
        }
        #pragma unroll
        for (int kk = 0; kk < 64; kk += 8) {
            const uint2 aA = *(const uint2*)&Ps[r0 * GP + kk + 2 * gc];
            const uint2 aB = *(const uint2*)&Ps[r1 * GP + kk + 2 * gc];
            #pragma unroll
            for (int c = 0; c < 4; c++) {
                const int d = wn * 32 + c * 8 + gr;
                const uint32_t b0 = Vs[(kk + gc) * GP + d];
                const uint32_t b1 = Vs[(kk + gc + 4) * GP + d];
                mma_tf32(o[c], aA.x, aB.x, aA.y, aB.y, b0, b1);
            }
        }

        // ---- m/l update ----
        if (wn == 0 && lane < 16) {
            const int rw = wm * 16 + lane;
            const float mo = m_s[rw];
            const float mn = fmaxf(mo, fmaxf(pmax[rw], pmax[64 + rw]));
            l_s[rw] = l_s[rw] * __expf(mo - mn) + psum[rw] + psum[64 + rw];
            m_s[rw] = mn;
        }
    }
    __syncthreads();

    const float inv0 = 1.0f / l_s[r0];
    const float inv1 = 1.0f / l_s[r1];
    #pragma unroll
    for (int c = 0; c < 4; c++) {
        const int d = head * HD + wn * 32 + c * 8 + gc * 2;
        *(float2*)(g_hcat + (size_t)(q0 + r0) * (HEADS * HD) + d) =
            make_float2(o[c][0] * inv0, o[c][1] * inv0);
        *(float2*)(g_hcat + (size_t)(q0 + r1) * (HEADS * HD) + d) =
            make_float2(o[c][2] * inv1, o[c][3] * inv1);
    }
}

// ---------------------------------------------------------------------------
extern "C" void kernel_launch(void* const* d_in, const int* in_sizes, int n_in,
                              void* d_out, int out_size)
{
    const float* X    = (const float*)d_in[0];
    const int*   mask = (const int*)  d_in[1];
    const float* WQ   = (const float*)d_in[2];
    const float* WK   = (const float*)d_in[3];
    const float* WV   = (const float*)d_in[4];
    const float* WO   = (const float*)d_in[5];
    float* out = (float*)d_out;

    const int gemm_smem = (128 + 64) * GP * 4;           // 55296 B
    const int attn_smem = 4 * 64 * GP * 4 + 384 * 4;     // 75264 B

    static int configured = 0;
    if (!configured) {
        cudaFuncSetAttribute(qkv_tf32_kernel,  cudaFuncAttributeMaxDynamicSharedMemorySize, gemm_smem);
        cudaFuncSetAttribute(proj_tf32_kernel, cudaFuncAttributeMaxDynamicSharedMemorySize, gemm_smem);
        cudaFuncSetAttribute(attn_kernel,      cudaFuncAttributeMaxDynamicSharedMemorySize, attn_smem);
        configured = 1;
    }

    qkv_tf32_kernel<<<dim3(NSEQ / 128, 3, HEADS), 256, gemm_smem>>>(X, WQ, WK, WV);
    attn_kernel<<<dim3(NSEQ / 64, HEADS), 256, attn_smem>>>(mask);
    proj_tf32_kernel<<<dim3(NSEQ / 128, FOUT / 64), 256, gemm_smem>>>(WO, out);
}

// round 11
// speedup vs baseline: 1.7052x; 1.2071x over previous
#include <cuda_runtime.h>
#include <cstdint>

#define HEADS 8
#define NSEQ  4096
#define FIN   512
#define HD    64
#define FOUT  512
#define NEG_INF -1e30f

// Scratch (allocation-free rule: __device__ globals)
__device__ float g_q[HEADS * NSEQ * HD];
__device__ float g_k[HEADS * NSEQ * HD];
__device__ float g_v[HEADS * NSEQ * HD];
__device__ float g_hcat[NSEQ * HEADS * HD];

__device__ __forceinline__ uint32_t f2tf(float f) {
    uint32_t r;
    asm("cvt.rna.tf32.f32 %0, %1;" : "=r"(r) : "f"(f));
    return r;
}

// pack two floats to f16x2: low half = lo, high half = hi
__device__ __forceinline__ uint32_t pack_f16(float lo, float hi) {
    uint32_t r;
    asm("cvt.rn.f16x2.f32 %0, %1, %2;" : "=r"(r) : "f"(hi), "f"(lo));
    return r;
}

__device__ __forceinline__ void mma_tf32(float c[4],
    uint32_t a0, uint32_t a1, uint32_t a2, uint32_t a3,
    uint32_t b0, uint32_t b1)
{
    asm volatile(
        "mma.sync.aligned.m16n8k8.row.col.f32.tf32.tf32.f32 "
        "{%0,%1,%2,%3}, {%4,%5,%6,%7}, {%8,%9}, {%0,%1,%2,%3};"
        : "+f"(c[0]), "+f"(c[1]), "+f"(c[2]), "+f"(c[3])
        : "r"(a0), "r"(a1), "r"(a2), "r"(a3), "r"(b0), "r"(b1));
}

__device__ __forceinline__ void mma_f16(float c[4],
    uint32_t a0, uint32_t a1, uint32_t a2, uint32_t a3,
    uint32_t b0, uint32_t b1)
{
    asm volatile(
        "mma.sync.aligned.m16n8k16.row.col.f32.f16.f16.f32 "
        "{%0,%1,%2,%3}, {%4,%5,%6,%7}, {%8,%9}, {%0,%1,%2,%3};"
        : "+f"(c[0]), "+f"(c[1]), "+f"(c[2]), "+f"(c[3])
        : "r"(a0), "r"(a1), "r"(a2), "r"(a3), "r"(b0), "r"(b1));
}

// ===========================================================================
// Shared TF32 NT-GEMM tile: C[128x64] = A[128x512] * B[64x512]^T.
// Pair-packed smem (pitch 72): group-of-8 col j at (j&3)*2 + (j>>2) ->
// each MMA operand pair (k+gc, k+gc+4) is one conflict-free LDS.64.
// ===========================================================================
#define GP 72

__device__ __forceinline__ void gemm_tile_tf32(
    const float* __restrict__ A, const float* __restrict__ B,
    float* __restrict__ C, int ldC)
{
    extern __shared__ uint32_t smg[];
    uint32_t* As = smg;              // 128*GP
    uint32_t* Bs = smg + 128 * GP;   // 64*GP

    const int tid  = threadIdx.x;
    const int warp = tid >> 5;
    const int lane = tid & 31;
    const int wm   = warp >> 1;
    const int wn   = warp & 1;
    const int gr   = lane >> 2;
    const int gc   = lane & 3;

    float acc[2][4][4];
    #pragma unroll
    for (int i = 0; i < 2; i++)
        #pragma unroll
        for (int c = 0; c < 4; c++)
            #pragma unroll
            for (int j = 0; j < 4; j++) acc[i][c][j] = 0.0f;

    const int r    = tid >> 4;        // 0..15
    const int c4i  = tid & 15;        // float4 column index
    const int pb   = (c4i >> 1) * 8 + (c4i & 1);  // packed base within row

    for (int k0 = 0; k0 < FIN; k0 += 64) {
        #pragma unroll
        for (int rr = 0; rr < 8; rr++) {
            float4 v = *(const float4*)(A + (size_t)(r + rr * 16) * FIN + k0 + c4i * 4);
            uint32_t* p = As + (r + rr * 16) * GP + pb;
            p[0] = f2tf(v.x); p[2] = f2tf(v.y); p[4] = f2tf(v.z); p[6] = f2tf(v.w);
        }
        #pragma unroll
        for (int rr = 0; rr < 4; rr++) {
            float4 v = *(const float4*)(B + (size_t)(r + rr * 16) * FIN + k0 + c4i * 4);
            uint32_t* p = Bs + (r + rr * 16) * GP + pb;
            p[0] = f2tf(v.x); p[2] = f2tf(v.y); p[4] = f2tf(v.z); p[6] = f2tf(v.w);
        }
        __syncthreads();

        #pragma unroll
        for (int kk = 0; kk < 64; kk += 8) {
            uint2 a[2][2];
            #pragma unroll
            for (int i = 0; i < 2; i++) {
                a[i][0] = *(const uint2*)&As[(wm * 32 + i * 16 + gr) * GP + kk + 2 * gc];
                a[i][1] = *(const uint2*)&As[(wm * 32 + i * 16 + 8 + gr) * GP + kk + 2 * gc];
            }
            #pragma unroll
            for (int c = 0; c < 4; c++) {
                uint2 b = *(const uint2*)&Bs[(wn * 32 + c * 8 + gr) * GP + kk + 2 * gc];
                #pragma unroll
                for (int i = 0; i < 2; i++)
                    mma_tf32(acc[i][c], a[i][0].x, a[i][1].x, a[i][0].y, a[i][1].y, b.x, b.y);
            }
        }
        __syncthreads();
    }

    #pragma unroll
    for (int i = 0; i < 2; i++)
        #pragma unroll
        for (int c = 0; c < 4; c++) {
            const int row = wm * 32 + i * 16 + gr;
            const int col = wn * 32 + c * 8 + gc * 2;
            *(float2*)&C[(size_t)row * ldC + col]       = make_float2(acc[i][c][0], acc[i][c][1]);
            *(float2*)&C[(size_t)(row + 8) * ldC + col] = make_float2(acc[i][c][2], acc[i][c][3]);
        }
}

// Kernel 1: QKV projection via TF32 GEMM. grid = (32 row-tiles, 3 mats, 8 heads)
__global__ void __launch_bounds__(256) qkv_tf32_kernel(
    const float* __restrict__ X,
    const float* __restrict__ WQ,
    const float* __restrict__ WK,
    const float* __restrict__ WV)
{
    const int head  = blockIdx.z;
    const int which = blockIdx.y;
    const int m0    = blockIdx.x * 128;
    const float* A = X + (size_t)head * NSEQ * FIN + (size_t)m0 * FIN;
    const float* W = (which == 0 ? WQ : which == 1 ? WK : WV) + (size_t)head * HD * FIN;
    float* C = (which == 0 ? g_q : which == 1 ? g_k : g_v)
               + (size_t)head * NSEQ * HD + (size_t)m0 * HD;
    gemm_tile_tf32(A, W, C, HD);
}

// Kernel 3: output projection via TF32 GEMM. grid = (32 row-tiles, 8 col-tiles)
__global__ void __launch_bounds__(256) proj_tf32_kernel(
    const float* __restrict__ WO, float* __restrict__ out)
{
    const int m0 = blockIdx.x * 128;
    const int n0 = blockIdx.y * 64;
    const float* A = g_hcat + (size_t)m0 * (HEADS * HD);
    const float* B = WO + (size_t)n0 * (HEADS * HD);
    float* C = out + (size_t)m0 * FOUT + n0;
    gemm_tile_tf32(A, B, C, FOUT);
}

// ===========================================================================
// Kernel 2: flash-attention v3 (R9 structure, fp16 PV path for precision).
//  - S = QK^T via tf32 m16n8k8 (pair-packed Q/K smem, LDS.64 operands)
//  - P kept in REGISTERS, converted to f16 A-fragments of m16n8k16
//  - PV via f16 m16n8k16; V stored as key-pair-packed f16x2 in smem
//  - per-warp partial O + partial l in regs; single combine at end.
// ===========================================================================
#define VP 72

__global__ void __launch_bounds__(256) attn_kernel(const int* __restrict__ mask)
{
    extern __shared__ uint32_t sm[];
    uint32_t* Qs  = sm;                        // 64*GP packed tf32
    uint32_t* Ks  = Qs + 64 * GP;              // 64*GP packed tf32
    uint32_t* Vsp = Ks + 64 * GP;              // 32*VP f16x2 (key pairs)
    float* pmax = (float*)(Vsp + 32 * VP);     // [2][64]

    const int head = blockIdx.y;
    const int q0   = blockIdx.x * 64;
    const int tid  = threadIdx.x;
    const int warp = tid >> 5;
    const int lane = tid & 31;
    const int wm   = warp >> 1;                // 0..3
    const int wn   = warp & 1;                 // 0..1  (key-slice)
    const int gr   = lane >> 2;                // 0..7
    const int gc   = lane & 3;                 // 0..3

    const float* Q = g_q + (size_t)head * NSEQ * HD;
    const float* K = g_k + (size_t)head * NSEQ * HD;
    const float* V = g_v + (size_t)head * NSEQ * HD;
    const int*   M = mask + (size_t)head * NSEQ * NSEQ;

    const int r   = tid >> 4;                  // 0..15
    const int c4i = tid & 15;
    const int c4  = c4i * 4;
    const int pb  = (c4i >> 1) * 8 + (c4i & 1);
    const int kp  = tid >> 4;                  // V pair index base (0..15)

    // Load Q tile -> packed tf32 smem
    #pragma unroll
    for (int rr = 0; rr < 4; rr++) {
        float4 v = *(const float4*)(Q + (size_t)(q0 + r + rr * 16) * HD + c4);
        uint32_t* p = Qs + (r + rr * 16) * GP + pb;
        p[0] = f2tf(v.x); p[2] = f2tf(v.y); p[4] = f2tf(v.z); p[6] = f2tf(v.w);
    }

    // Per-warp partial state (registers)
    float m0 = -3e38f, m1 = -3e38f;            // running row max (shared value)
    float l0 = 0.0f,  l1 = 0.0f;               // THIS warp's partial row sum
    float o[8][4];                             // partial O: rows r0/r1 x 64 d
    #pragma unroll
    for (int c = 0; c < 8; c++)
        #pragma unroll
        for (int j = 0; j < 4; j++) o[c][j] = 0.0f;

    const int r0 = wm * 16 + gr;
    const int r1 = r0 + 8;

    for (int kt = 0; kt < NSEQ / 64; kt++) {
        const int k0 = kt * 64;
        __syncthreads();  // sync1: previous iteration fully consumed

        // K tile -> packed tf32
        #pragma unroll
        for (int rr = 0; rr < 4; rr++) {
            float4 kv = *(const float4*)(K + (size_t)(k0 + r + rr * 16) * HD + c4);
            uint32_t* pk = Ks + (r + rr * 16) * GP + pb;
            pk[0] = f2tf(kv.x); pk[2] = f2tf(kv.y); pk[4] = f2tf(kv.z); pk[6] = f2tf(kv.w);
        }
        // V tile -> key-pair-packed f16x2: Vsp[pair][d] = {V[2p][d], V[2p+1][d]}
        #pragma unroll
        for (int pass = 0; pass < 2; pass++) {
            const int kpp = kp + pass * 16;    // 0..31
            float4 v0 = *(const float4*)(V + (size_t)(k0 + 2 * kpp)     * HD + c4);
            float4 v1 = *(const float4*)(V + (size_t)(k0 + 2 * kpp + 1) * HD + c4);
            uint32_t* pv = Vsp + kpp * VP + c4;
            pv[0] = pack_f16(v0.x, v1.x);
            pv[1] = pack_f16(v0.y, v1.y);
            pv[2] = pack_f16(v0.z, v1.z);
            pv[3] = pack_f16(v0.w, v1.w);
        }
        // Mask fragments (C-fragment coords)
        int2 mk[4][2];
        #pragma unroll
        for (int c = 0; c < 4; c++) {
            const int col = k0 + wn * 32 + c * 8 + gc * 2;
            mk[c][0] = *(const int2*)(M + (size_t)(q0 + r0) * NSEQ + col);
            mk[c][1] = *(const int2*)(M + (size_t)(q0 + r1) * NSEQ + col);
        }
        __syncthreads();  // sync2: tiles ready

        // ---- S = Q K^T (tf32) ----
        float sc[4][4];
        #pragma unroll
        for (int c = 0; c < 4; c++)
            #pragma unroll
            for (int j = 0; j < 4; j++) sc[c][j] = 0.0f;

        #pragma unroll
        for (int kk = 0; kk < 64; kk += 8) {
            const uint2 aA = *(const uint2*)&Qs[r0 * GP + kk + 2 * gc];
            const uint2 aB = *(const uint2*)&Qs[r1 * GP + kk + 2 * gc];
            #pragma unroll
            for (int c = 0; c < 4; c++) {
                const uint2 b = *(const uint2*)&Ks[(wn * 32 + c * 8 + gr) * GP + kk + 2 * gc];
                mma_tf32(sc[c], aA.x, aB.x, aA.y, aB.y, b.x, b.y);
            }
        }

        // ---- scale + mask ----
        #pragma unroll
        for (int c = 0; c < 4; c++) {
            sc[c][0] = mk[c][0].x ? sc[c][0] * 0.125f : NEG_INF;
            sc[c][1] = mk[c][0].y ? sc[c][1] * 0.125f : NEG_INF;
            sc[c][2] = mk[c][1].x ? sc[c][2] * 0.125f : NEG_INF;
            sc[c][3] = mk[c][1].y ? sc[c][3] * 0.125f : NEG_INF;
        }

        // ---- partial row max -> smem exchange ----
        float rm0 = -3e38f, rm1 = -3e38f;
        #pragma unroll
        for (int c = 0; c < 4; c++) {
            rm0 = fmaxf(rm0, fmaxf(sc[c][0], sc[c][1]));
            rm1 = fmaxf(rm1, fmaxf(sc[c][2], sc[c][3]));
        }
        rm0 = fmaxf(rm0, __shfl_xor_sync(0xFFFFFFFFu, rm0, 1));
        rm0 = fmaxf(rm0, __shfl_xor_sync(0xFFFFFFFFu, rm0, 2));
        rm1 = fmaxf(rm1, __shfl_xor_sync(0xFFFFFFFFu, rm1, 1));
        rm1 = fmaxf(rm1, __shfl_xor_sync(0xFFFFFFFFu, rm1, 2));
        if (gc == 0) { pmax[wn * 64 + r0] = rm0; pmax[wn * 64 + r1] = rm1; }
        __syncthreads();  // sync3: pmax visible

        const float mn0 = fmaxf(m0, fmaxf(pmax[r0], pmax[64 + r0]));
        const float mn1 = fmaxf(m1, fmaxf(pmax[r1], pmax[64 + r1]));
        const float al0 = __expf(m0 - mn0);
        const float al1 = __expf(m1 - mn1);
        m0 = mn0; m1 = mn1;

        // ---- exp (registers), partial row sums, l update ----
        float rs0 = 0.0f, rs1 = 0.0f;
        #pragma unroll
        for (int c = 0; c < 4; c++) {
            sc[c][0] = __expf(sc[c][0] - mn0);
            sc[c][1] = __expf(sc[c][1] - mn0);
            sc[c][2] = __expf(sc[c][2] - mn1);
            sc[c][3] = __expf(sc[c][3] - mn1);
            rs0 += sc[c][0] + sc[c][1];
            rs1 += sc[c][2] + sc[c][3];
        }
        rs0 += __shfl_xor_sync(0xFFFFFFFFu, rs0, 1);
        rs0 += __shfl_xor_sync(0xFFFFFFFFu, rs0, 2);
        rs1 += __shfl_xor_sync(0xFFFFFFFFu, rs1, 1);
        rs1 += __shfl_xor_sync(0xFFFFFFFFu, rs1, 2);
        l0 = l0 * al0 + rs0;
        l1 = l1 * al1 + rs1;

        // ---- O rescale + O += P V  (f16 m16n8k16, P from registers) ----
        #pragma unroll
        for (int c = 0; c < 8; c++) {
            o[c][0] *= al0; o[c][1] *= al0;
            o[c][2] *= al1; o[c][3] *= al1;
        }
        #pragma unroll
        for (int s = 0; s < 2; s++) {          // 16 keys per step
            const uint32_t a0 = pack_f16(sc[2*s][0],   sc[2*s][1]);
            const uint32_t a1 = pack_f16(sc[2*s][2],   sc[2*s][3]);
            const uint32_t a2 = pack_f16(sc[2*s+1][0], sc[2*s+1][1]);
            const uint32_t a3 = pack_f16(sc[2*s+1][2], sc[2*s+1][3]);
            const int kpb = wn * 16 + s * 8 + gc;   // V pair row for b0
            #pragma unroll
            for (int c = 0; c < 8; c++) {
                const int d = c * 8 + gr;
                const uint32_t b0 = Vsp[kpb * VP + d];
                const uint32_t b1 = Vsp[(kpb + 4) * VP + d];
                mma_f16(o[c], a0, a1, a2, a3, b0, b1);
            }
        }
    }
    __syncthreads();  // loop done; smem tiles free for combine

    // ---- cross-warp combine: O = O_wn0 + O_wn1, l = l0 + l1 ----
    float* Os = (float*)sm;          // [64][65]
    float* Ls = Os + 64 * 65;        // [64]
    if (wn == 1) {
        #pragma unroll
        for (int c = 0; c < 8; c++) {
            const int d = c * 8 + gc * 2;
            Os[r0 * 65 + d] = o[c][0]; Os[r0 * 65 + d + 1] = o[c][1];
            Os[r1 * 65 + d] = o[c][2]; Os[r1 * 65 + d + 1] = o[c][3];
        }
        if (gc == 0) { Ls[r0] = l0; Ls[r1] = l1; }
    }
    __syncthreads();
    if (wn == 0) {
        const float inv0 = 1.0f / (l0 + Ls[r0]);
        const float inv1 = 1.0f / (l1 + Ls[r1]);
        #pragma unroll
        for (int c = 0; c < 8; c++) {
            const int dl = c * 8 + gc * 2;
            const int d  = head * HD + dl;
            *(float2*)(g_hcat + (size_t)(q0 + r0) * (HEADS * HD) + d) =
                make_float2((o[c][0] + Os[r0 * 65 + dl]) * inv0,
                            (o[c][1] + Os[r0 * 65 + dl + 1]) * inv0);
            *(float2*)(g_hcat + (size_t)(q0 + r1) * (HEADS * HD) + d) =
                make_float2((o[c][2] + Os[r1 * 65 + dl]) * inv1,
                            (o[c][3] + Os[r1 * 65 + dl + 1]) * inv1);
        }
    }
}

// ---------------------------------------------------------------------------
extern "C" void kernel_launch(void* const* d_in, const int* in_sizes, int n_in,
                              void* d_out, int out_size)
{
    const float* X    = (const float*)d_in[0];
    const int*   mask = (const int*)  d_in[1];
    const float* WQ   = (const float*)d_in[2];
    const float* WK   = (const float*)d_in[3];
    const float* WV   = (const float*)d_in[4];
    const float* WO   = (const float*)d_in[5];
    float* out = (float*)d_out;

    const int gemm_smem = (128 + 64) * GP * 4;                    // 55296 B
    const int attn_smem = (2 * 64 * GP + 32 * VP + 128) * 4;      // 46592 B

    static int configured = 0;
    if (!configured) {
        cudaFuncSetAttribute(qkv_tf32_kernel,  cudaFuncAttributeMaxDynamicSharedMemorySize, gemm_smem);
        cudaFuncSetAttribute(proj_tf32_kernel, cudaFuncAttributeMaxDynamicSharedMemorySize, gemm_smem);
        cudaFuncSetAttribute(attn_kernel,      cudaFuncAttributeMaxDynamicSharedMemorySize, attn_smem);
        configured = 1;
    }

    qkv_tf32_kernel<<<dim3(NSEQ / 128, 3, HEADS), 256, gemm_smem>>>(X, WQ, WK, WV);
    attn_kernel<<<dim3(NSEQ / 64, HEADS), 256, attn_smem>>>(mask);
    proj_tf32_kernel<<<dim3(NSEQ / 128, FOUT / 64), 256, gemm_smem>>>(WO, out);
}

// round 12
// speedup vs baseline: 1.9024x; 1.1157x over previous
#include <cuda_runtime.h>
#include <cstdint>

#define HEADS 8
#define NSEQ  4096
#define FIN   512
#define HD    64
#define FOUT  512
#define NEG_INF -1e30f

// Scratch (allocation-free rule: __device__ globals)
__device__ float g_q[HEADS * NSEQ * HD];
__device__ float g_k[HEADS * NSEQ * HD];
__device__ float g_v[HEADS * NSEQ * HD];
__device__ float g_hcat[NSEQ * HEADS * HD];

__device__ __forceinline__ uint32_t f2tf(float f) {
    uint32_t r;
    asm("cvt.rna.tf32.f32 %0, %1;" : "=r"(r) : "f"(f));
    return r;
}

// pack two floats to f16x2: low half = lo, high half = hi
__device__ __forceinline__ uint32_t pack_f16(float lo, float hi) {
    uint32_t r;
    asm("cvt.rn.f16x2.f32 %0, %1, %2;" : "=r"(r) : "f"(hi), "f"(lo));
    return r;
}

__device__ __forceinline__ void mma_tf32(float c[4],
    uint32_t a0, uint32_t a1, uint32_t a2, uint32_t a3,
    uint32_t b0, uint32_t b1)
{
    asm volatile(
        "mma.sync.aligned.m16n8k8.row.col.f32.tf32.tf32.f32 "
        "{%0,%1,%2,%3}, {%4,%5,%6,%7}, {%8,%9}, {%0,%1,%2,%3};"
        : "+f"(c[0]), "+f"(c[1]), "+f"(c[2]), "+f"(c[3])
        : "r"(a0), "r"(a1), "r"(a2), "r"(a3), "r"(b0), "r"(b1));
}

__device__ __forceinline__ void mma_f16(float c[4],
    uint32_t a0, uint32_t a1, uint32_t a2, uint32_t a3,
    uint32_t b0, uint32_t b1)
{
    asm volatile(
        "mma.sync.aligned.m16n8k16.row.col.f32.f16.f16.f32 "
        "{%0,%1,%2,%3}, {%4,%5,%6,%7}, {%8,%9}, {%0,%1,%2,%3};"
        : "+f"(c[0]), "+f"(c[1]), "+f"(c[2]), "+f"(c[3])
        : "r"(a0), "r"(a1), "r"(a2), "r"(a3), "r"(b0), "r"(b1));
}

// ===========================================================================
// Shared TF32 NT-GEMM tile: C[128x64] = A[128x512] * B[64x512]^T.
// Pair-packed smem (pitch 72): group-of-8 col j at (j&3)*2 + (j>>2) ->
// each MMA operand pair (k+gc, k+gc+4) is one conflict-free LDS.64.
// ===========================================================================
#define GP 72

__device__ __forceinline__ void gemm_tile_tf32(
    const float* __restrict__ A, const float* __restrict__ B,
    float* __restrict__ C, int ldC)
{
    extern __shared__ uint32_t smg[];
    uint32_t* As = smg;              // 128*GP
    uint32_t* Bs = smg + 128 * GP;   // 64*GP

    const int tid  = threadIdx.x;
    const int warp = tid >> 5;
    const int lane = tid & 31;
    const int wm   = warp >> 1;
    const int wn   = warp & 1;
    const int gr   = lane >> 2;
    const int gc   = lane & 3;

    float acc[2][4][4];
    #pragma unroll
    for (int i = 0; i < 2; i++)
        #pragma unroll
        for (int c = 0; c < 4; c++)
            #pragma unroll
            for (int j = 0; j < 4; j++) acc[i][c][j] = 0.0f;

    const int r    = tid >> 4;        // 0..15
    const int c4i  = tid & 15;        // float4 column index
    const int pb   = (c4i >> 1) * 8 + (c4i & 1);  // packed base within row

    for (int k0 = 0; k0 < FIN; k0 += 64) {
        #pragma unroll
        for (int rr = 0; rr < 8; rr++) {
            float4 v = *(const float4*)(A + (size_t)(r + rr * 16) * FIN + k0 + c4i * 4);
            uint32_t* p = As + (r + rr * 16) * GP + pb;
            p[0] = f2tf(v.x); p[2] = f2tf(v.y); p[4] = f2tf(v.z); p[6] = f2tf(v.w);
        }
        #pragma unroll
        for (int rr = 0; rr < 4; rr++) {
            float4 v = *(const float4*)(B + (size_t)(r + rr * 16) * FIN + k0 + c4i * 4);
            uint32_t* p = Bs + (r + rr * 16) * GP + pb;
            p[0] = f2tf(v.x); p[2] = f2tf(v.y); p[4] = f2tf(v.z); p[6] = f2tf(v.w);
        }
        __syncthreads();

        #pragma unroll
        for (int kk = 0; kk < 64; kk += 8) {
            uint2 a[2][2];
            #pragma unroll
            for (int i = 0; i < 2; i++) {
                a[i][0] = *(const uint2*)&As[(wm * 32 + i * 16 + gr) * GP + kk + 2 * gc];
                a[i][1] = *(const uint2*)&As[(wm * 32 + i * 16 + 8 + gr) * GP + kk + 2 * gc];
            }
            #pragma unroll
            for (int c = 0; c < 4; c++) {
                uint2 b = *(const uint2*)&Bs[(wn * 32 + c * 8 + gr) * GP + kk + 2 * gc];
                #pragma unroll
                for (int i = 0; i < 2; i++)
                    mma_tf32(acc[i][c], a[i][0].x, a[i][1].x, a[i][0].y, a[i][1].y, b.x, b.y);
            }
        }
        __syncthreads();
    }

    #pragma unroll
    for (int i = 0; i < 2; i++)
        #pragma unroll
        for (int c = 0; c < 4; c++) {
            const int row = wm * 32 + i * 16 + gr;
            const int col = wn * 32 + c * 8 + gc * 2;
            *(float2*)&C[(size_t)row * ldC + col]       = make_float2(acc[i][c][0], acc[i][c][1]);
            *(float2*)&C[(size_t)(row + 8) * ldC + col] = make_float2(acc[i][c][2], acc[i][c][3]);
        }
}

// Kernel 1: QKV projection via TF32 GEMM. grid = (32 row-tiles, 3 mats, 8 heads)
__global__ void __launch_bounds__(256) qkv_tf32_kernel(
    const float* __restrict__ X,
    const float* __restrict__ WQ,
    const float* __restrict__ WK,
    const float* __restrict__ WV)
{
    const int head  = blockIdx.z;
    const int which = blockIdx.y;
    const int m0    = blockIdx.x * 128;
    const float* A = X + (size_t)head * NSEQ * FIN + (size_t)m0 * FIN;
    const float* W = (which == 0 ? WQ : which == 1 ? WK : WV) + (size_t)head * HD * FIN;
    float* C = (which == 0 ? g_q : which == 1 ? g_k : g_v)
               + (size_t)head * NSEQ * HD + (size_t)m0 * HD;
    gemm_tile_tf32(A, W, C, HD);
}

// Kernel 3: output projection via TF32 GEMM. grid = (32 row-tiles, 8 col-tiles)
__global__ void __launch_bounds__(256) proj_tf32_kernel(
    const float* __restrict__ WO, float* __restrict__ out)
{
    const int m0 = blockIdx.x * 128;
    const int n0 = blockIdx.y * 64;
    const float* A = g_hcat + (size_t)m0 * (HEADS * HD);
    const float* B = WO + (size_t)n0 * (HEADS * HD);
    float* C = out + (size_t)m0 * FOUT + n0;
    gemm_tile_tf32(A, B, C, FOUT);
}

// ===========================================================================
// Kernel 2: flash-attention v4 (all-fp16 tensor paths, fp32 softmax/accum).
//  - S = QK^T via f16 m16n8k16: Q/K in smem as pair-packed f16x2 words
//    (word j of each 8-group at (j&3)*2+(j>>2); pitch 40 => conflict-free
//    two-phase LDS.64).
//  - P in registers -> f16 A-fragments; PV via f16 m16n8k16 (R10 path).
//  - per-warp partial O + partial l in regs; single combine at end.
// ===========================================================================
#define QP2 40
#define VP  72

__global__ void __launch_bounds__(256) attn_kernel(const int* __restrict__ mask)
{
    extern __shared__ uint32_t sm[];
    uint32_t* Qs  = sm;                        // 64*QP2 packed f16x2
    uint32_t* Ks  = Qs + 64 * QP2;             // 64*QP2 packed f16x2
    uint32_t* Vsp = Ks + 64 * QP2;             // 32*VP f16x2 (key pairs)
    float* pmax = (float*)(Vsp + 32 * VP);     // [2][64]

    const int head = blockIdx.y;
    const int q0   = blockIdx.x * 64;
    const int tid  = threadIdx.x;
    const int warp = tid >> 5;
    const int lane = tid & 31;
    const int wm   = warp >> 1;                // 0..3
    const int wn   = warp & 1;                 // 0..1  (key-slice)
    const int gr   = lane >> 2;                // 0..7
    const int gc   = lane & 3;                 // 0..3

    const float* Q = g_q + (size_t)head * NSEQ * HD;
    const float* K = g_k + (size_t)head * NSEQ * HD;
    const float* V = g_v + (size_t)head * NSEQ * HD;
    const int*   M = mask + (size_t)head * NSEQ * NSEQ;

    const int r   = tid >> 4;                  // 0..15
    const int c4i = tid & 15;
    const int c4  = c4i * 4;
    const int kp  = tid >> 4;                  // V pair index base (0..15)

    // f16x2 word indices this thread writes (words cover k=2w, 2w+1)
    const int w0 = 2 * c4i, w1 = 2 * c4i + 1;
    const int p0 = (w0 >> 3) * 8 + ((w0 & 3) << 1) + ((w0 >> 2) & 1);
    const int p1 = (w1 >> 3) * 8 + ((w1 & 3) << 1) + ((w1 >> 2) & 1);

    // Load Q tile -> pair-packed f16x2 smem
    #pragma unroll
    for (int rr = 0; rr < 4; rr++) {
        float4 v = *(const float4*)(Q + (size_t)(q0 + r + rr * 16) * HD + c4);
        uint32_t* p = Qs + (r + rr * 16) * QP2;
        p[p0] = pack_f16(v.x, v.y);
        p[p1] = pack_f16(v.z, v.w);
    }

    // Per-warp partial state (registers)
    float m0 = -3e38f, m1 = -3e38f;            // running row max (shared value)
    float l0 = 0.0f,  l1 = 0.0f;               // THIS warp's partial row sum
    float o[8][4];                             // partial O: rows r0/r1 x 64 d
    #pragma unroll
    for (int c = 0; c < 8; c++)
        #pragma unroll
        for (int j = 0; j < 4; j++) o[c][j] = 0.0f;

    const int r0 = wm * 16 + gr;
    const int r1 = r0 + 8;

    for (int kt = 0; kt < NSEQ / 64; kt++) {
        const int k0 = kt * 64;
        __syncthreads();  // sync1: previous iteration fully consumed

        // K tile -> pair-packed f16x2
        #pragma unroll
        for (int rr = 0; rr < 4; rr++) {
            float4 kv = *(const float4*)(K + (size_t)(k0 + r + rr * 16) * HD + c4);
            uint32_t* pk = Ks + (r + rr * 16) * QP2;
            pk[p0] = pack_f16(kv.x, kv.y);
            pk[p1] = pack_f16(kv.z, kv.w);
        }
        // V tile -> key-pair-packed f16x2: Vsp[pair][d] = {V[2p][d], V[2p+1][d]}
        #pragma unroll
        for (int pass = 0; pass < 2; pass++) {
            const int kpp = kp + pass * 16;    // 0..31
            float4 v0 = *(const float4*)(V + (size_t)(k0 + 2 * kpp)     * HD + c4);
            float4 v1 = *(const float4*)(V + (size_t)(k0 + 2 * kpp + 1) * HD + c4);
            uint32_t* pv = Vsp + kpp * VP + c4;
            pv[0] = pack_f16(v0.x, v1.x);
            pv[1] = pack_f16(v0.y, v1.y);
            pv[2] = pack_f16(v0.z, v1.z);
            pv[3] = pack_f16(v0.w, v1.w);
        }
        // Mask fragments (C-fragment coords)
        int2 mk[4][2];
        #pragma unroll
        for (int c = 0; c < 4; c++) {
            const int col = k0 + wn * 32 + c * 8 + gc * 2;
            mk[c][0] = *(const int2*)(M + (size_t)(q0 + r0) * NSEQ + col);
            mk[c][1] = *(const int2*)(M + (size_t)(q0 + r1) * NSEQ + col);
        }
        __syncthreads();  // sync2: tiles ready

        // ---- S = Q K^T (f16 m16n8k16) ----
        float sc[4][4];
        #pragma unroll
        for (int c = 0; c < 4; c++)
            #pragma unroll
            for (int j = 0; j < 4; j++) sc[c][j] = 0.0f;

        #pragma unroll
        for (int s = 0; s < 4; s++) {          // 16 k per step
            const uint2 aA = *(const uint2*)&Qs[r0 * QP2 + s * 8 + 2 * gc];  // a0,a2
            const uint2 aB = *(const uint2*)&Qs[r1 * QP2 + s * 8 + 2 * gc];  // a1,a3
            #pragma unroll
            for (int c = 0; c < 4; c++) {
                const uint2 b = *(const uint2*)&Ks[(wn * 32 + c * 8 + gr) * QP2 + s * 8 + 2 * gc];
                mma_f16(sc[c], aA.x, aB.x, aA.y, aB.y, b.x, b.y);
            }
        }

        // ---- scale + mask ----
        #pragma unroll
        for (int c = 0; c < 4; c++) {
            sc[c][0] = mk[c][0].x ? sc[c][0] * 0.125f : NEG_INF;
            sc[c][1] = mk[c][0].y ? sc[c][1] * 0.125f : NEG_INF;
            sc[c][2] = mk[c][1].x ? sc[c][2] * 0.125f : NEG_INF;
            sc[c][3] = mk[c][1].y ? sc[c][3] * 0.125f : NEG_INF;
        }

        // ---- partial row max -> smem exchange ----
        float rm0 = -3e38f, rm1 = -3e38f;
        #pragma unroll
        for (int c = 0; c < 4; c++) {
            rm0 = fmaxf(rm0, fmaxf(sc[c][0], sc[c][1]));
            rm1 = fmaxf(rm1, fmaxf(sc[c][2], sc[c][3]));
        }
        rm0 = fmaxf(rm0, __shfl_xor_sync(0xFFFFFFFFu, rm0, 1));
        rm0 = fmaxf(rm0, __shfl_xor_sync(0xFFFFFFFFu, rm0, 2));
        rm1 = fmaxf(rm1, __shfl_xor_sync(0xFFFFFFFFu, rm1, 1));
        rm1 = fmaxf(rm1, __shfl_xor_sync(0xFFFFFFFFu, rm1, 2));
        if (gc == 0) { pmax[wn * 64 + r0] = rm0; pmax[wn * 64 + r1] = rm1; }
        __syncthreads();  // sync3: pmax visible

        const float mn0 = fmaxf(m0, fmaxf(pmax[r0], pmax[64 + r0]));
        const float mn1 = fmaxf(m1, fmaxf(pmax[r1], pmax[64 + r1]));
        const float al0 = __expf(m0 - mn0);
        const float al1 = __expf(m1 - mn1);
        m0 = mn0; m1 = mn1;

        // ---- exp (registers), partial row sums, l update ----
        float rs0 = 0.0f, rs1 = 0.0f;
        #pragma unroll
        for (int c = 0; c < 4; c++) {
            sc[c][0] = __expf(sc[c][0] - mn0);
            sc[c][1] = __expf(sc[c][1] - mn0);
            sc[c][2] = __expf(sc[c][2] - mn1);
            sc[c][3] = __expf(sc[c][3] - mn1);
            rs0 += sc[c][0] + sc[c][1];
            rs1 += sc[c][2] + sc[c][3];
        }
        rs0 += __shfl_xor_sync(0xFFFFFFFFu, rs0, 1);
        rs0 += __shfl_xor_sync(0xFFFFFFFFu, rs0, 2);
        rs1 += __shfl_xor_sync(0xFFFFFFFFu, rs1, 1);
        rs1 += __shfl_xor_sync(0xFFFFFFFFu, rs1, 2);
        l0 = l0 * al0 + rs0;
        l1 = l1 * al1 + rs1;

        // ---- O rescale + O += P V  (f16 m16n8k16, P from registers) ----
        #pragma unroll
        for (int c = 0; c < 8; c++) {
            o[c][0] *= al0; o[c][1] *= al0;
            o[c][2] *= al1; o[c][3] *= al1;
        }
        #pragma unroll
        for (int s = 0; s < 2; s++) {          // 16 keys per step
            const uint32_t a0 = pack_f16(sc[2*s][0],   sc[2*s][1]);
            const uint32_t a1 = pack_f16(sc[2*s][2],   sc[2*s][3]);
            const uint32_t a2 = pack_f16(sc[2*s+1][0], sc[2*s+1][1]);
            const uint32_t a3 = pack_f16(sc[2*s+1][2], sc[2*s+1][3]);
            const int kpb = wn * 16 + s * 8 + gc;   // V pair row for b0
            #pragma unroll
            for (int c = 0; c < 8; c++) {
                const int d = c * 8 + gr;
                const uint32_t b0 = Vsp[kpb * VP + d];
                const uint32_t b1 = Vsp[(kpb + 4) * VP + d];
                mma_f16(o[c], a0, a1, a2, a3, b0, b1);
            }
        }
    }
    __syncthreads();  // loop done; smem tiles free for combine

    // ---- cross-warp combine: O = O_wn0 + O_wn1, l = l0 + l1 ----
    float* Os = (float*)sm;          // [64][65]
    float* Ls = Os + 64 * 65;        // [64]
    if (wn == 1) {
        #pragma unroll
        for (int c = 0; c < 8; c++) {
            const int d = c * 8 + gc * 2;
            Os[r0 * 65 + d] = o[c][0]; Os[r0 * 65 + d + 1] = o[c][1];
            Os[r1 * 65 + d] = o[c][2]; Os[r1 * 65 + d + 1] = o[c][3];
        }
        if (gc == 0) { Ls[r0] = l0; Ls[r1] = l1; }
    }
    __syncthreads();
    if (wn == 0) {
        const float inv0 = 1.0f / (l0 + Ls[r0]);
        const float inv1 = 1.0f / (l1 + Ls[r1]);
        #pragma unroll
        for (int c = 0; c < 8; c++) {
            const int dl = c * 8 + gc * 2;
            const int d  = head * HD + dl;
            *(float2*)(g_hcat + (size_t)(q0 + r0) * (HEADS * HD) + d) =
                make_float2((o[c][0] + Os[r0 * 65 + dl]) * inv0,
                            (o[c][1] + Os[r0 * 65 + dl + 1]) * inv0);
            *(float2*)(g_hcat + (size_t)(q0 + r1) * (HEADS * HD) + d) =
                make_float2((o[c][2] + Os[r1 * 65 + dl]) * inv1,
                            (o[c][3] + Os[r1 * 65 + dl + 1]) * inv1);
        }
    }
}

// ---------------------------------------------------------------------------
extern "C" void kernel_launch(void* const* d_in, const int* in_sizes, int n_in,
                              void* d_out, int out_size)
{
    const float* X    = (const float*)d_in[0];
    const int*   mask = (const int*)  d_in[1];
    const float* WQ   = (const float*)d_in[2];
    const float* WK   = (const float*)d_in[3];
    const float* WV   = (const float*)d_in[4];
    const float* WO   = (const float*)d_in[5];
    float* out = (float*)d_out;

    const int gemm_smem = (128 + 64) * GP * 4;                        // 55296 B
    const int attn_smem = (2 * 64 * QP2 + 32 * VP + 128) * 4;         // 30208 B

    static int configured = 0;
    if (!configured) {
        cudaFuncSetAttribute(qkv_tf32_kernel,  cudaFuncAttributeMaxDynamicSharedMemorySize, gemm_smem);
        cudaFuncSetAttribute(proj_tf32_kernel, cudaFuncAttributeMaxDynamicSharedMemorySize, gemm_smem);
        cudaFuncSetAttribute(attn_kernel,      cudaFuncAttributeMaxDynamicSharedMemorySize, attn_smem);
        configured = 1;
    }

    qkv_tf32_kernel<<<dim3(NSEQ / 128, 3, HEADS), 256, gemm_smem>>>(X, WQ, WK, WV);
    attn_kernel<<<dim3(NSEQ / 64, HEADS), 256, attn_smem>>>(mask);
    proj_tf32_kernel<<<dim3(NSEQ / 128, FOUT / 64), 256, gemm_smem>>>(WO, out);
}

// round 13
// speedup vs baseline: 2.5126x; 1.3207x over previous
#include <cuda_runtime.h>
#include <cstdint>

#define HEADS 8
#define NSEQ  4096
#define FIN   512
#define HD    64
#define FOUT  512
#define NEG_INF -1e30f

// Scratch (allocation-free rule: __device__ globals)
__device__ float g_q[HEADS * NSEQ * HD];
__device__ float g_k[HEADS * NSEQ * HD];
__device__ float g_v[HEADS * NSEQ * HD];
__device__ float g_hcat[NSEQ * HEADS * HD];

// pack two floats to f16x2: low half = lo, high half = hi
__device__ __forceinline__ uint32_t pack_f16(float lo, float hi) {
    uint32_t r;
    asm("cvt.rn.f16x2.f32 %0, %1, %2;" : "=r"(r) : "f"(hi), "f"(lo));
    return r;
}

__device__ __forceinline__ void mma_f16(float c[4],
    uint32_t a0, uint32_t a1, uint32_t a2, uint32_t a3,
    uint32_t b0, uint32_t b1)
{
    asm volatile(
        "mma.sync.aligned.m16n8k16.row.col.f32.f16.f16.f32 "
        "{%0,%1,%2,%3}, {%4,%5,%6,%7}, {%8,%9}, {%0,%1,%2,%3};"
        : "+f"(c[0]), "+f"(c[1]), "+f"(c[2]), "+f"(c[3])
        : "r"(a0), "r"(a1), "r"(a2), "r"(a3), "r"(b0), "r"(b1));
}

// ===========================================================================
// FP16 NT-GEMM tile: C[128x64] = A[128x512] * B[64x512]^T (fp32 accum).
// f16x2 words pair-packed per 8-word group: word j at (j&3)*2+(j>>2).
// Pitch 40 words (==8 mod 32): every fragment uint2 load is conflict-free.
// ===========================================================================
#define HP 40

__device__ __forceinline__ void gemm_tile_f16(
    const float* __restrict__ A, const float* __restrict__ B,
    float* __restrict__ C, int ldC)
{
    extern __shared__ uint32_t smg[];
    uint32_t* As = smg;              // 128*HP
    uint32_t* Bs = smg + 128 * HP;   // 64*HP

    const int tid  = threadIdx.x;
    const int warp = tid >> 5;
    const int lane = tid & 31;
    const int wm   = warp >> 1;
    const int wn   = warp & 1;
    const int gr   = lane >> 2;
    const int gc   = lane & 3;

    float acc[2][4][4];
    #pragma unroll
    for (int i = 0; i < 2; i++)
        #pragma unroll
        for (int c = 0; c < 4; c++)
            #pragma unroll
            for (int j = 0; j < 4; j++) acc[i][c][j] = 0.0f;

    const int r   = tid >> 4;        // 0..15
    const int c4i = tid & 15;        // float4 column index within 64-float k-block
    const int w0  = 2 * c4i, w1 = 2 * c4i + 1;
    const int p0  = (w0 >> 3) * 8 + ((w0 & 3) << 1) + ((w0 >> 2) & 1);
    const int p1  = (w1 >> 3) * 8 + ((w1 & 3) << 1) + ((w1 >> 2) & 1);

    for (int k0 = 0; k0 < FIN; k0 += 64) {
        #pragma unroll
        for (int rr = 0; rr < 8; rr++) {
            float4 v = *(const float4*)(A + (size_t)(r + rr * 16) * FIN + k0 + c4i * 4);
            uint32_t* p = As + (r + rr * 16) * HP;
            p[p0] = pack_f16(v.x, v.y);
            p[p1] = pack_f16(v.z, v.w);
        }
        #pragma unroll
        for (int rr = 0; rr < 4; rr++) {
            float4 v = *(const float4*)(B + (size_t)(r + rr * 16) * FIN + k0 + c4i * 4);
            uint32_t* p = Bs + (r + rr * 16) * HP;
            p[p0] = pack_f16(v.x, v.y);
            p[p1] = pack_f16(v.z, v.w);
        }
        __syncthreads();

        #pragma unroll
        for (int s = 0; s < 4; s++) {          // k16 per step
            uint2 a[2][2];
            #pragma unroll
            for (int i = 0; i < 2; i++) {
                a[i][0] = *(const uint2*)&As[(wm * 32 + i * 16 + gr) * HP + s * 8 + 2 * gc];
                a[i][1] = *(const uint2*)&As[(wm * 32 + i * 16 + 8 + gr) * HP + s * 8 + 2 * gc];
            }
            #pragma unroll
            for (int c = 0; c < 4; c++) {
                uint2 b = *(const uint2*)&Bs[(wn * 32 + c * 8 + gr) * HP + s * 8 + 2 * gc];
                #pragma unroll
                for (int i = 0; i < 2; i++)
                    mma_f16(acc[i][c], a[i][0].x, a[i][1].x, a[i][0].y, a[i][1].y, b.x, b.y);
            }
        }
        __syncthreads();
    }

    #pragma unroll
    for (int i = 0; i < 2; i++)
        #pragma unroll
        for (int c = 0; c < 4; c++) {
            const int row = wm * 32 + i * 16 + gr;
            const int col = wn * 32 + c * 8 + gc * 2;
            *(float2*)&C[(size_t)row * ldC + col]       = make_float2(acc[i][c][0], acc[i][c][1]);
            *(float2*)&C[(size_t)(row + 8) * ldC + col] = make_float2(acc[i][c][2], acc[i][c][3]);
        }
}

// Kernel 1: QKV projection via FP16 GEMM. grid = (32 row-tiles, 3 mats, 8 heads)
__global__ void __launch_bounds__(256) qkv_kernel(
    const float* __restrict__ X,
    const float* __restrict__ WQ,
    const float* __restrict__ WK,
    const float* __restrict__ WV)
{
    const int head  = blockIdx.z;
    const int which = blockIdx.y;
    const int m0    = blockIdx.x * 128;
    const float* A = X + (size_t)head * NSEQ * FIN + (size_t)m0 * FIN;
    const float* W = (which == 0 ? WQ : which == 1 ? WK : WV) + (size_t)head * HD * FIN;
    float* C = (which == 0 ? g_q : which == 1 ? g_k : g_v)
               + (size_t)head * NSEQ * HD + (size_t)m0 * HD;
    gemm_tile_f16(A, W, C, HD);
}

// Kernel 3: output projection via FP16 GEMM. grid = (32 row-tiles, 8 col-tiles)
__global__ void __launch_bounds__(256) proj_kernel(
    const float* __restrict__ WO, float* __restrict__ out)
{
    const int m0 = blockIdx.x * 128;
    const int n0 = blockIdx.y * 64;
    const float* A = g_hcat + (size_t)m0 * (HEADS * HD);
    const float* B = WO + (size_t)n0 * (HEADS * HD);
    float* C = out + (size_t)m0 * FOUT + n0;
    gemm_tile_f16(A, B, C, FOUT);
}

// ===========================================================================
// Kernel 2: flash-attention v5 (R11 + Q fragments hoisted to registers).
// ===========================================================================
#define QP2 40
#define VP  72

__global__ void __launch_bounds__(256) attn_kernel(const int* __restrict__ mask)
{
    extern __shared__ uint32_t sm[];
    uint32_t* Qs  = sm;                        // 64*QP2 packed f16x2 (preamble only)
    uint32_t* Ks  = Qs + 64 * QP2;             // 64*QP2 packed f16x2
    uint32_t* Vsp = Ks + 64 * QP2;             // 32*VP f16x2 (key pairs)
    float* pmax = (float*)(Vsp + 32 * VP);     // [2][64]

    const int head = blockIdx.y;
    const int q0   = blockIdx.x * 64;
    const int tid  = threadIdx.x;
    const int warp = tid >> 5;
    const int lane = tid & 31;
    const int wm   = warp >> 1;                // 0..3
    const int wn   = warp & 1;                 // 0..1  (key-slice)
    const int gr   = lane >> 2;                // 0..7
    const int gc   = lane & 3;                 // 0..3

    const float* Q = g_q + (size_t)head * NSEQ * HD;
    const float* K = g_k + (size_t)head * NSEQ * HD;
    const float* V = g_v + (size_t)head * NSEQ * HD;
    const int*   M = mask + (size_t)head * NSEQ * NSEQ;

    const int r   = tid >> 4;                  // 0..15
    const int c4i = tid & 15;
    const int c4  = c4i * 4;
    const int kp  = tid >> 4;                  // V pair index base (0..15)

    const int w0 = 2 * c4i, w1 = 2 * c4i + 1;
    const int p0 = (w0 >> 3) * 8 + ((w0 & 3) << 1) + ((w0 >> 2) & 1);
    const int p1 = (w1 >> 3) * 8 + ((w1 & 3) << 1) + ((w1 >> 2) & 1);

    const int r0 = wm * 16 + gr;
    const int r1 = r0 + 8;

    // Load Q tile -> pair-packed f16x2 smem, then hoist fragments to regs
    #pragma unroll
    for (int rr = 0; rr < 4; rr++) {
        float4 v = *(const float4*)(Q + (size_t)(q0 + r + rr * 16) * HD + c4);
        uint32_t* p = Qs + (r + rr * 16) * QP2;
        p[p0] = pack_f16(v.x, v.y);
        p[p1] = pack_f16(v.z, v.w);
    }
    __syncthreads();
    uint2 qa[4], qb[4];                        // loop-invariant A-fragments
    #pragma unroll
    for (int s = 0; s < 4; s++) {
        qa[s] = *(const uint2*)&Qs[r0 * QP2 + s * 8 + 2 * gc];
        qb[s] = *(const uint2*)&Qs[r1 * QP2 + s * 8 + 2 * gc];
    }

    // Per-warp partial state (registers)
    float m0 = -3e38f, m1 = -3e38f;
    float l0 = 0.0f,  l1 = 0.0f;
    float o[8][4];
    #pragma unroll
    for (int c = 0; c < 8; c++)
        #pragma unroll
        for (int j = 0; j < 4; j++) o[c][j] = 0.0f;

    for (int kt = 0; kt < NSEQ / 64; kt++) {
        const int k0 = kt * 64;
        __syncthreads();  // sync1: previous iteration fully consumed

        // K tile -> pair-packed f16x2
        #pragma unroll
        for (int rr = 0; rr < 4; rr++) {
            float4 kv = *(const float4*)(K + (size_t)(k0 + r + rr * 16) * HD + c4);
            uint32_t* pk = Ks + (r + rr * 16) * QP2;
            pk[p0] = pack_f16(kv.x, kv.y);
            pk[p1] = pack_f16(kv.z, kv.w);
        }
        // V tile -> key-pair-packed f16x2
        #pragma unroll
        for (int pass = 0; pass < 2; pass++) {
            const int kpp = kp + pass * 16;
            float4 v0 = *(const float4*)(V + (size_t)(k0 + 2 * kpp)     * HD + c4);
            float4 v1 = *(const float4*)(V + (size_t)(k0 + 2 * kpp + 1) * HD + c4);
            uint32_t* pv = Vsp + kpp * VP + c4;
            pv[0] = pack_f16(v0.x, v1.x);
            pv[1] = pack_f16(v0.y, v1.y);
            pv[2] = pack_f16(v0.z, v1.z);
            pv[3] = pack_f16(v0.w, v1.w);
        }
        // Mask fragments
        int2 mk[4][2];
        #pragma unroll
        for (int c = 0; c < 4; c++) {
            const int col = k0 + wn * 32 + c * 8 + gc * 2;
            mk[c][0] = *(const int2*)(M + (size_t)(q0 + r0) * NSEQ + col);
            mk[c][1] = *(const int2*)(M + (size_t)(q0 + r1) * NSEQ + col);
        }
        __syncthreads();  // sync2: tiles ready

        // ---- S = Q K^T (f16 m16n8k16, Q from registers) ----
        float sc[4][4];
        #pragma unroll
        for (int c = 0; c < 4; c++)
            #pragma unroll
            for (int j = 0; j < 4; j++) sc[c][j] = 0.0f;

        #pragma unroll
        for (int s = 0; s < 4; s++) {
            #pragma unroll
            for (int c = 0; c < 4; c++) {
                const uint2 b = *(const uint2*)&Ks[(wn * 32 + c * 8 + gr) * QP2 + s * 8 + 2 * gc];
                mma_f16(sc[c], qa[s].x, qb[s].x, qa[s].y, qb[s].y, b.x, b.y);
            }
        }

        // ---- scale + mask ----
        #pragma unroll
        for (int c = 0; c < 4; c++) {
            sc[c][0] = mk[c][0].x ? sc[c][0] * 0.125f : NEG_INF;
            sc[c][1] = mk[c][0].y ? sc[c][1] * 0.125f : NEG_INF;
            sc[c][2] = mk[c][1].x ? sc[c][2] * 0.125f : NEG_INF;
            sc[c][3] = mk[c][1].y ? sc[c][3] * 0.125f : NEG_INF;
        }

        // ---- partial row max -> smem exchange ----
        float rm0 = -3e38f, rm1 = -3e38f;
        #pragma unroll
        for (int c = 0; c < 4; c++) {
            rm0 = fmaxf(rm0, fmaxf(sc[c][0], sc[c][1]));
            rm1 = fmaxf(rm1, fmaxf(sc[c][2], sc[c][3]));
        }
        rm0 = fmaxf(rm0, __shfl_xor_sync(0xFFFFFFFFu, rm0, 1));
        rm0 = fmaxf(rm0, __shfl_xor_sync(0xFFFFFFFFu, rm0, 2));
        rm1 = fmaxf(rm1, __shfl_xor_sync(0xFFFFFFFFu, rm1, 1));
        rm1 = fmaxf(rm1, __shfl_xor_sync(0xFFFFFFFFu, rm1, 2));
        if (gc == 0) { pmax[wn * 64 + r0] = rm0; pmax[wn * 64 + r1] = rm1; }
        __syncthreads();  // sync3: pmax visible

        const float mn0 = fmaxf(m0, fmaxf(pmax[r0], pmax[64 + r0]));
        const float mn1 = fmaxf(m1, fmaxf(pmax[r1], pmax[64 + r1]));
        const float al0 = __expf(m0 - mn0);
        const float al1 = __expf(m1 - mn1);
        m0 = mn0; m1 = mn1;

        // ---- exp, partial sums, l update ----
        float rs0 = 0.0f, rs1 = 0.0f;
        #pragma unroll
        for (int c = 0; c < 4; c++) {
            sc[c][0] = __expf(sc[c][0] - mn0);
            sc[c][1] = __expf(sc[c][1] - mn0);
            sc[c][2] = __expf(sc[c][2] - mn1);
            sc[c][3] = __expf(sc[c][3] - mn1);
            rs0 += sc[c][0] + sc[c][1];
            rs1 += sc[c][2] + sc[c][3];
        }
        rs0 += __shfl_xor_sync(0xFFFFFFFFu, rs0, 1);
        rs0 += __shfl_xor_sync(0xFFFFFFFFu, rs0, 2);
        rs1 += __shfl_xor_sync(0xFFFFFFFFu, rs1, 1);
        rs1 += __shfl_xor_sync(0xFFFFFFFFu, rs1, 2);
        l0 = l0 * al0 + rs0;
        l1 = l1 * al1 + rs1;

        // ---- O rescale + O += P V ----
        #pragma unroll
        for (int c = 0; c < 8; c++) {
            o[c][0] *= al0; o[c][1] *= al0;
            o[c][2] *= al1; o[c][3] *= al1;
        }
        #pragma unroll
        for (int s = 0; s < 2; s++) {
            const uint32_t a0 = pack_f16(sc[2*s][0],   sc[2*s][1]);
            const uint32_t a1 = pack_f16(sc[2*s][2],   sc[2*s][3]);
            const uint32_t a2 = pack_f16(sc[2*s+1][0], sc[2*s+1][1]);
            const uint32_t a3 = pack_f16(sc[2*s+1][2], sc[2*s+1][3]);
            const int kpb = wn * 16 + s * 8 + gc;
            #pragma unroll
            for (int c = 0; c < 8; c++) {
                const int d = c * 8 + gr;
                const uint32_t b0 = Vsp[kpb * VP + d];
                const uint32_t b1 = Vsp[(kpb + 4) * VP + d];
                mma_f16(o[c], a0, a1, a2, a3, b0, b1);
            }
        }
    }
    __syncthreads();  // loop done; smem free for combine

    // ---- cross-warp combine ----
    float* Os = (float*)sm;          // [64][65]
    float* Ls = Os + 64 * 65;        // [64]
    if (wn == 1) {
        #pragma unroll
        for (int c = 0; c < 8; c++) {
            const int d = c * 8 + gc * 2;
            Os[r0 * 65 + d] = o[c][0]; Os[r0 * 65 + d + 1] = o[c][1];
            Os[r1 * 65 + d] = o[c][2]; Os[r1 * 65 + d + 1] = o[c][3];
        }
        if (gc == 0) { Ls[r0] = l0; Ls[r1] = l1; }
    }
    __syncthreads();
    if (wn == 0) {
        const float inv0 = 1.0f / (l0 + Ls[r0]);
        const float inv1 = 1.0f / (l1 + Ls[r1]);
        #pragma unroll
        for (int c = 0; c < 8; c++) {
            const int dl = c * 8 + gc * 2;
            const int d  = head * HD + dl;
            *(float2*)(g_hcat + (size_t)(q0 + r0) * (HEADS * HD) + d) =
                make_float2((o[c][0] + Os[r0 * 65 + dl]) * inv0,
                            (o[c][1] + Os[r0 * 65 + dl + 1]) * inv0);
            *(float2*)(g_hcat + (size_t)(q0 + r1) * (HEADS * HD) + d) =
                make_float2((o[c][2] + Os[r1 * 65 + dl]) * inv1,
                            (o[c][3] + Os[r1 * 65 + dl + 1]) * inv1);
        }
    }
}

// ---------------------------------------------------------------------------
extern "C" void kernel_launch(void* const* d_in, const int* in_sizes, int n_in,
                              void* d_out, int out_size)
{
    const float* X    = (const float*)d_in[0];
    const int*   mask = (const int*)  d_in[1];
    const float* WQ   = (const float*)d_in[2];
    const float* WK   = (const float*)d_in[3];
    const float* WV   = (const float*)d_in[4];
    const float* WO   = (const float*)d_in[5];
    float* out = (float*)d_out;

    const int gemm_smem = (128 + 64) * HP * 4;                        // 30720 B
    const int attn_smem = (2 * 64 * QP2 + 32 * VP + 128) * 4;         // 30208 B

    static int configured = 0;
    if (!configured) {
        cudaFuncSetAttribute(qkv_kernel,  cudaFuncAttributeMaxDynamicSharedMemorySize, gemm_smem);
        cudaFuncSetAttribute(proj_kernel, cudaFuncAttributeMaxDynamicSharedMemorySize, gemm_smem);
        cudaFuncSetAttribute(attn_kernel, cudaFuncAttributeMaxDynamicSharedMemorySize, attn_smem);
        configured = 1;
    }

    qkv_kernel<<<dim3(NSEQ / 128, 3, HEADS), 256, gemm_smem>>>(X, WQ, WK, WV);
    attn_kernel<<<dim3(NSEQ / 64, HEADS), 256, attn_smem>>>(mask);
    proj_kernel<<<dim3(NSEQ / 128, FOUT / 64), 256, gemm_smem>>>(WO, out);
}

// round 14
// speedup vs baseline: 2.6031x; 1.0360x over previous
#include <cuda_runtime.h>
#include <cstdint>

#define HEADS 8
#define NSEQ  4096
#define FIN   512
#define HD    64
#define FOUT  512
#define NEG_INF -1e30f

// Scratch (allocation-free rule: __device__ globals).
// Q/K: pair-packed f16x2 rows, 32 words/row.  V: key-pair f16x2, [pair][64].
// hcat: pair-packed f16x2 rows, 256 words/row.
__device__ uint32_t g_qh[HEADS * NSEQ * 32];
__device__ uint32_t g_kh[HEADS * NSEQ * 32];
__device__ uint32_t g_vp[HEADS * (NSEQ / 2) * 64];
__device__ uint32_t g_hcat[NSEQ * 256];

// pack two floats to f16x2: low half = lo, high half = hi
__device__ __forceinline__ uint32_t pack_f16(float lo, float hi) {
    uint32_t r;
    asm("cvt.rn.f16x2.f32 %0, %1, %2;" : "=r"(r) : "f"(hi), "f"(lo));
    return r;
}

__device__ __forceinline__ void mma_f16(float c[4],
    uint32_t a0, uint32_t a1, uint32_t a2, uint32_t a3,
    uint32_t b0, uint32_t b1)
{
    asm volatile(
        "mma.sync.aligned.m16n8k16.row.col.f32.f16.f16.f32 "
        "{%0,%1,%2,%3}, {%4,%5,%6,%7}, {%8,%9}, {%0,%1,%2,%3};"
        : "+f"(c[0]), "+f"(c[1]), "+f"(c[2]), "+f"(c[3])
        : "r"(a0), "r"(a1), "r"(a2), "r"(a3), "r"(b0), "r"(b1));
}

// pair-packed position of word j within its 8-word group
__device__ __forceinline__ int ppos(int w) {
    return (w >> 3) * 8 + ((w & 3) << 1) + ((w >> 2) & 1);
}

#define HP 40   // smem word pitch for 32-word rows (==8 mod 32)
#define VP 72   // smem word pitch for 64-word V rows (==8 mod 32)

// ===========================================================================
// Kernel 1: QKV projection. FP16 MMA mainloop (fp32 in, f16 out).
// which==0/1 (Q/K): pair-packed f16x2 rows. which==2 (V): key-pair via shfl.
// ===========================================================================
__global__ void __launch_bounds__(256) qkv_kernel(
    const float* __restrict__ X,
    const float* __restrict__ WQ,
    const float* __restrict__ WK,
    const float* __restrict__ WV)
{
    extern __shared__ uint32_t smg[];
    uint32_t* As = smg;              // 128*HP
    uint32_t* Bs = smg + 128 * HP;   // 64*HP

    const int head  = blockIdx.z;
    const int which = blockIdx.y;
    const int m0    = blockIdx.x * 128;
    const float* A = X + (size_t)head * NSEQ * FIN + (size_t)m0 * FIN;
    const float* W = (which == 0 ? WQ : which == 1 ? WK : WV) + (size_t)head * HD * FIN;

    const int tid  = threadIdx.x;
    const int warp = tid >> 5;
    const int lane = tid & 31;
    const int wm   = warp >> 1;
    const int wn   = warp & 1;
    const int gr   = lane >> 2;
    const int gc   = lane & 3;

    float acc[2][4][4];
    #pragma unroll
    for (int i = 0; i < 2; i++)
        #pragma unroll
        for (int c = 0; c < 4; c++)
            #pragma unroll
            for (int j = 0; j < 4; j++) acc[i][c][j] = 0.0f;

    const int r   = tid >> 4;
    const int c4i = tid & 15;
    const int w0  = 2 * c4i, w1 = 2 * c4i + 1;
    const int p0  = ppos(w0), p1 = ppos(w1);

    for (int k0 = 0; k0 < FIN; k0 += 64) {
        #pragma unroll
        for (int rr = 0; rr < 8; rr++) {
            float4 v = *(const float4*)(A + (size_t)(r + rr * 16) * FIN + k0 + c4i * 4);
            uint32_t* p = As + (r + rr * 16) * HP;
            p[p0] = pack_f16(v.x, v.y);
            p[p1] = pack_f16(v.z, v.w);
        }
        #pragma unroll
        for (int rr = 0; rr < 4; rr++) {
            float4 v = *(const float4*)(W + (size_t)(r + rr * 16) * FIN + k0 + c4i * 4);
            uint32_t* p = Bs + (r + rr * 16) * HP;
            p[p0] = pack_f16(v.x, v.y);
            p[p1] = pack_f16(v.z, v.w);
        }
        __syncthreads();

        #pragma unroll
        for (int s = 0; s < 4; s++) {
            uint2 a[2][2];
            #pragma unroll
            for (int i = 0; i < 2; i++) {
                a[i][0] = *(const uint2*)&As[(wm * 32 + i * 16 + gr) * HP + s * 8 + 2 * gc];
                a[i][1] = *(const uint2*)&As[(wm * 32 + i * 16 + 8 + gr) * HP + s * 8 + 2 * gc];
            }
            #pragma unroll
            for (int c = 0; c < 4; c++) {
                uint2 b = *(const uint2*)&Bs[(wn * 32 + c * 8 + gr) * HP + s * 8 + 2 * gc];
                #pragma unroll
                for (int i = 0; i < 2; i++)
                    mma_f16(acc[i][c], a[i][0].x, a[i][1].x, a[i][0].y, a[i][1].y, b.x, b.y);
            }
        }
        __syncthreads();
    }

    if (which < 2) {
        // Q/K: pair-packed f16x2 rows
        uint32_t* out = (which == 0 ? g_qh : g_kh) + (size_t)head * NSEQ * 32;
        #pragma unroll
        for (int i = 0; i < 2; i++)
            #pragma unroll
            for (int c = 0; c < 4; c++) {
                const int row = m0 + wm * 32 + i * 16 + gr;
                const int p   = ppos(wn * 16 + c * 4 + gc);
                out[(size_t)row * 32 + p]       = pack_f16(acc[i][c][0], acc[i][c][1]);
                out[(size_t)(row + 8) * 32 + p] = pack_f16(acc[i][c][2], acc[i][c][3]);
            }
    } else {
        // V: key-pair-packed f16x2 [pair][d] via shfl across gr parity
        uint32_t* out = g_vp + (size_t)head * (NSEQ / 2) * 64;
        #pragma unroll
        for (int i = 0; i < 2; i++)
            #pragma unroll
            for (int c = 0; c < 4; c++) {
                const float t0 = __shfl_xor_sync(0xFFFFFFFFu, acc[i][c][0], 4);
                const float t1 = __shfl_xor_sync(0xFFFFFFFFu, acc[i][c][1], 4);
                const float t2 = __shfl_xor_sync(0xFFFFFFFFu, acc[i][c][2], 4);
                const float t3 = __shfl_xor_sync(0xFFFFFFFFu, acc[i][c][3], 4);
                const int base = m0 + wm * 32 + i * 16;
                const int n0   = wn * 32 + c * 8 + gc * 2;
                if (!(gr & 1)) {
                    const int pe = (base + gr) >> 1;           // rows base+gr, base+gr+1
                    out[(size_t)pe * 64 + n0]     = pack_f16(acc[i][c][0], t0);
                    out[(size_t)pe * 64 + n0 + 1] = pack_f16(acc[i][c][1], t1);
                } else {
                    const int po = (base + 8 + gr - 1) >> 1;   // rows base+8+gr-1, base+8+gr
                    out[(size_t)po * 64 + n0]     = pack_f16(t2, acc[i][c][2]);
                    out[(size_t)po * 64 + n0 + 1] = pack_f16(t3, acc[i][c][3]);
                }
            }
    }
}

// ===========================================================================
// Kernel 3: output projection. A = hcat (pair-packed f16, straight copy),
// B = WO fp32 (cvt path). fp32 output.
// ===========================================================================
__global__ void __launch_bounds__(256) proj_kernel(
    const float* __restrict__ WO, float* __restrict__ out)
{
    extern __shared__ uint32_t smg[];
    uint32_t* As = smg;              // 128*HP
    uint32_t* Bs = smg + 128 * HP;   // 64*HP

    const int m0  = blockIdx.x * 128;
    const int n0  = blockIdx.y * 64;
    const float* B = WO + (size_t)n0 * (HEADS * HD);

    const int tid  = threadIdx.x;
    const int warp = tid >> 5;
    const int lane = tid & 31;
    const int wm   = warp >> 1;
    const int wn   = warp & 1;
    const int gr   = lane >> 2;
    const int gc   = lane & 3;

    float acc[2][4][4];
    #pragma unroll
    for (int i = 0; i < 2; i++)
        #pragma unroll
        for (int c = 0; c < 4; c++)
            #pragma unroll
            for (int j = 0; j < 4; j++) acc[i][c][j] = 0.0f;

    const int rh  = tid >> 1;        // 0..127 (A copy row)
    const int hh  = tid & 1;
    const int r   = tid >> 4;
    const int c4i = tid & 15;
    const int p0  = ppos(2 * c4i), p1 = ppos(2 * c4i + 1);

    for (int k0 = 0; k0 < HEADS * HD; k0 += 64) {
        const int k0w = k0 >> 1;
        // A: straight f16 copy (already pair-packed in global)
        #pragma unroll
        for (int q = 0; q < 4; q++) {
            const int o = hh * 16 + q * 4;
            *(uint4*)&As[rh * HP + o] =
                *(const uint4*)(g_hcat + (size_t)(m0 + rh) * 256 + k0w + o);
        }
        // B: fp32 -> f16 pair-packed
        #pragma unroll
        for (int rr = 0; rr < 4; rr++) {
            float4 v = *(const float4*)(B + (size_t)(r + rr * 16) * (HEADS * HD) + k0 + c4i * 4);
            uint32_t* p = Bs + (r + rr * 16) * HP;
            p[p0] = pack_f16(v.x, v.y);
            p[p1] = pack_f16(v.z, v.w);
        }
        __syncthreads();

        #pragma unroll
        for (int s = 0; s < 4; s++) {
            uint2 a[2][2];
            #pragma unroll
            for (int i = 0; i < 2; i++) {
                a[i][0] = *(const uint2*)&As[(wm * 32 + i * 16 + gr) * HP + s * 8 + 2 * gc];
                a[i][1] = *(const uint2*)&As[(wm * 32 + i * 16 + 8 + gr) * HP + s * 8 + 2 * gc];
            }
            #pragma unroll
            for (int c = 0; c < 4; c++) {
                uint2 b = *(const uint2*)&Bs[(wn * 32 + c * 8 + gr) * HP + s * 8 + 2 * gc];
                #pragma unroll
                for (int i = 0; i < 2; i++)
                    mma_f16(acc[i][c], a[i][0].x, a[i][1].x, a[i][0].y, a[i][1].y, b.x, b.y);
            }
        }
        __syncthreads();
    }

    #pragma unroll
    for (int i = 0; i < 2; i++)
        #pragma unroll
        for (int c = 0; c < 4; c++) {
            const int row = m0 + wm * 32 + i * 16 + gr;
            const int col = n0 + wn * 32 + c * 8 + gc * 2;
            *(float2*)&out[(size_t)row * FOUT + col]       = make_float2(acc[i][c][0], acc[i][c][1]);
            *(float2*)&out[(size_t)(row + 8) * FOUT + col] = make_float2(acc[i][c][2], acc[i][c][3]);
        }
}

// ===========================================================================
// Kernel 2: flash-attention v6. All tiles arrive as f16 straight copies
// (zero cvt in loop). Q frags hoisted; P in regs; per-warp partial O/l.
// ===========================================================================
__global__ void __launch_bounds__(256) attn_kernel(const int* __restrict__ mask)
{
    extern __shared__ uint32_t sm[];
    uint32_t* Qs  = sm;                        // 64*HP (preamble only)
    uint32_t* Ks  = Qs + 64 * HP;              // 64*HP
    uint32_t* Vsp = Ks + 64 * HP;              // 32*VP
    float* pmax = (float*)(Vsp + 32 * VP);     // [2][64]

    const int head = blockIdx.y;
    const int q0   = blockIdx.x * 64;
    const int tid  = threadIdx.x;
    const int warp = tid >> 5;
    const int lane = tid & 31;
    const int wm   = warp >> 1;
    const int wn   = warp & 1;
    const int gr   = lane >> 2;
    const int gc   = lane & 3;

    const uint32_t* Qg = g_qh + (size_t)head * NSEQ * 32;
    const uint32_t* Kg = g_kh + (size_t)head * NSEQ * 32;
    const uint32_t* Vg = g_vp + (size_t)head * (NSEQ / 2) * 64;
    const int*      M  = mask + (size_t)head * NSEQ * NSEQ;

    // copy thread mappings (conflict-free swizzles)
    const int r4 = tid >> 2;                   // 0..63 (Q/K row)
    const int qd = tid & 3;
    const int oA = (qd + 2 * (r4 & 1)) * 4;    // 0..20
    const int oB = oA ^ 16;
    const int pr = tid >> 3;                   // 0..31 (V pair)
    const int oV = (tid & 7) * 4;              // 0..28

    const int r0 = wm * 16 + gr;
    const int r1 = r0 + 8;

    // Q tile -> smem (straight copy), then hoist fragments
    {
        const uint32_t* src = Qg + (size_t)(q0 + r4) * 32;
        *(uint4*)&Qs[r4 * HP + oA] = *(const uint4*)(src + oA);
        *(uint4*)&Qs[r4 * HP + oB] = *(const uint4*)(src + oB);
    }
    __syncthreads();
    uint2 qa[4], qb[4];
    #pragma unroll
    for (int s = 0; s < 4; s++) {
        qa[s] = *(const uint2*)&Qs[r0 * HP + s * 8 + 2 * gc];
        qb[s] = *(const uint2*)&Qs[r1 * HP + s * 8 + 2 * gc];
    }

    float m0 = -3e38f, m1 = -3e38f;
    float l0 = 0.0f,  l1 = 0.0f;
    float o[8][4];
    #pragma unroll
    for (int c = 0; c < 8; c++)
        #pragma unroll
        for (int j = 0; j < 4; j++) o[c][j] = 0.0f;

    for (int kt = 0; kt < NSEQ / 64; kt++) {
        const int k0 = kt * 64;
        __syncthreads();  // sync1

        // K tile: straight f16 copy
        {
            const uint32_t* src = Kg + (size_t)(k0 + r4) * 32;
            *(uint4*)&Ks[r4 * HP + oA] = *(const uint4*)(src + oA);
            *(uint4*)&Ks[r4 * HP + oB] = *(const uint4*)(src + oB);
        }
        // V tile: straight f16 copy (key-pair layout preserved)
        {
            const uint32_t* src = Vg + (size_t)((k0 >> 1) + pr) * 64;
            *(uint4*)&Vsp[pr * VP + oV]      = *(const uint4*)(src + oV);
            *(uint4*)&Vsp[pr * VP + oV + 32] = *(const uint4*)(src + oV + 32);
        }
        // Mask fragments
        int2 mk[4][2];
        #pragma unroll
        for (int c = 0; c < 4; c++) {
            const int col = k0 + wn * 32 + c * 8 + gc * 2;
            mk[c][0] = *(const int2*)(M + (size_t)(q0 + r0) * NSEQ + col);
            mk[c][1] = *(const int2*)(M + (size_t)(q0 + r1) * NSEQ + col);
        }
        __syncthreads();  // sync2

        // ---- S = Q K^T ----
        float sc[4][4];
        #pragma unroll
        for (int c = 0; c < 4; c++)
            #pragma unroll
            for (int j = 0; j < 4; j++) sc[c][j] = 0.0f;

        #pragma unroll
        for (int s = 0; s < 4; s++) {
            #pragma unroll
            for (int c = 0; c < 4; c++) {
                const uint2 b = *(const uint2*)&Ks[(wn * 32 + c * 8 + gr) * HP + s * 8 + 2 * gc];
                mma_f16(sc[c], qa[s].x, qb[s].x, qa[s].y, qb[s].y, b.x, b.y);
            }
        }

        // ---- scale + mask ----
        #pragma unroll
        for (int c = 0; c < 4; c++) {
            sc[c][0] = mk[c][0].x ? sc[c][0] * 0.125f : NEG_INF;
            sc[c][1] = mk[c][0].y ? sc[c][1] * 0.125f : NEG_INF;
            sc[c][2] = mk[c][1].x ? sc[c][2] * 0.125f : NEG_INF;
            sc[c][3] = mk[c][1].y ? sc[c][3] * 0.125f : NEG_INF;
        }

        // ---- partial row max -> smem exchange ----
        float rm0 = -3e38f, rm1 = -3e38f;
        #pragma unroll
        for (int c = 0; c < 4; c++) {
            rm0 = fmaxf(rm0, fmaxf(sc[c][0], sc[c][1]));
            rm1 = fmaxf(rm1, fmaxf(sc[c][2], sc[c][3]));
        }
        rm0 = fmaxf(rm0, __shfl_xor_sync(0xFFFFFFFFu, rm0, 1));
        rm0 = fmaxf(rm0, __shfl_xor_sync(0xFFFFFFFFu, rm0, 2));
        rm1 = fmaxf(rm1, __shfl_xor_sync(0xFFFFFFFFu, rm1, 1));
        rm1 = fmaxf(rm1, __shfl_xor_sync(0xFFFFFFFFu, rm1, 2));
        if (gc == 0) { pmax[wn * 64 + r0] = rm0; pmax[wn * 64 + r1] = rm1; }
        __syncthreads();  // sync3

        const float mn0 = fmaxf(m0, fmaxf(pmax[r0], pmax[64 + r0]));
        const float mn1 = fmaxf(m1, fmaxf(pmax[r1], pmax[64 + r1]));
        const float al0 = __expf(m0 - mn0);
        const float al1 = __expf(m1 - mn1);
        m0 = mn0; m1 = mn1;

        // ---- exp, partial sums, l update ----
        float rs0 = 0.0f, rs1 = 0.0f;
        #pragma unroll
        for (int c = 0; c < 4; c++) {
            sc[c][0] = __expf(sc[c][0] - mn0);
            sc[c][1] = __expf(sc[c][1] - mn0);
            sc[c][2] = __expf(sc[c][2] - mn1);
            sc[c][3] = __expf(sc[c][3] - mn1);
            rs0 += sc[c][0] + sc[c][1];
            rs1 += sc[c][2] + sc[c][3];
        }
        rs0 += __shfl_xor_sync(0xFFFFFFFFu, rs0, 1);
        rs0 += __shfl_xor_sync(0xFFFFFFFFu, rs0, 2);
        rs1 += __shfl_xor_sync(0xFFFFFFFFu, rs1, 1);
        rs1 += __shfl_xor_sync(0xFFFFFFFFu, rs1, 2);
        l0 = l0 * al0 + rs0;
        l1 = l1 * al1 + rs1;

        // ---- O rescale + O += P V ----
        #pragma unroll
        for (int c = 0; c < 8; c++) {
            o[c][0] *= al0; o[c][1] *= al0;
            o[c][2] *= al1; o[c][3] *= al1;
        }
        #pragma unroll
        for (int s = 0; s < 2; s++) {
            const uint32_t a0 = pack_f16(sc[2*s][0],   sc[2*s][1]);
            const uint32_t a1 = pack_f16(sc[2*s][2],   sc[2*s][3]);
            const uint32_t a2 = pack_f16(sc[2*s+1][0], sc[2*s+1][1]);
            const uint32_t a3 = pack_f16(sc[2*s+1][2], sc[2*s+1][3]);
            const int kpb = wn * 16 + s * 8 + gc;
            #pragma unroll
            for (int c = 0; c < 8; c++) {
                const int d = c * 8 + gr;
                const uint32_t b0 = Vsp[kpb * VP + d];
                const uint32_t b1 = Vsp[(kpb + 4) * VP + d];
                mma_f16(o[c], a0, a1, a2, a3, b0, b1);
            }
        }
    }
    __syncthreads();  // loop done; smem free for combine

    // ---- cross-warp combine; write hcat as pair-packed f16 ----
    float* Os = (float*)sm;          // [64][65]
    float* Ls = Os + 64 * 65;        // [64]
    if (wn == 1) {
        #pragma unroll
        for (int c = 0; c < 8; c++) {
            const int d = c * 8 + gc * 2;
            Os[r0 * 65 + d] = o[c][0]; Os[r0 * 65 + d + 1] = o[c][1];
            Os[r1 * 65 + d] = o[c][2]; Os[r1 * 65 + d + 1] = o[c][3];
        }
        if (gc == 0) { Ls[r0] = l0; Ls[r1] = l1; }
    }
    __syncthreads();
    if (wn == 0) {
        const float inv0 = 1.0f / (l0 + Ls[r0]);
        const float inv1 = 1.0f / (l1 + Ls[r1]);
        #pragma unroll
        for (int c = 0; c < 8; c++) {
            const int dl = c * 8 + gc * 2;
            const int p  = ppos(head * 32 + c * 4 + gc);
            g_hcat[(size_t)(q0 + r0) * 256 + p] =
                pack_f16((o[c][0] + Os[r0 * 65 + dl]) * inv0,
                         (o[c][1] + Os[r0 * 65 + dl + 1]) * inv0);
            g_hcat[(size_t)(q0 + r1) * 256 + p] =
                pack_f16((o[c][2] + Os[r1 * 65 + dl]) * inv1,
                         (o[c][3] + Os[r1 * 65 + dl + 1]) * inv1);
        }
    }
}

// ---------------------------------------------------------------------------
extern "C" void kernel_launch(void* const* d_in, const int* in_sizes, int n_in,
                              void* d_out, int out_size)
{
    const float* X    = (const float*)d_in[0];
    const int*   mask = (const int*)  d_in[1];
    const float* WQ   = (const float*)d_in[2];
    const float* WK   = (const float*)d_in[3];
    const float* WV   = (const float*)d_in[4];
    const float* WO   = (const float*)d_in[5];
    float* out = (float*)d_out;

    const int gemm_smem = (128 + 64) * HP * 4;                    // 30720 B
    const int attn_smem = (2 * 64 * HP + 32 * VP + 128) * 4;      // 30208 B

    static int configured = 0;
    if (!configured) {
        cudaFuncSetAttribute(qkv_kernel,  cudaFuncAttributeMaxDynamicSharedMemorySize, gemm_smem);
        cudaFuncSetAttribute(proj_kernel, cudaFuncAttributeMaxDynamicSharedMemorySize, gemm_smem);
        cudaFuncSetAttribute(attn_kernel, cudaFuncAttributeMaxDynamicSharedMemorySize, attn_smem);
        configured = 1;
    }

    qkv_kernel<<<dim3(NSEQ / 128, 3, HEADS), 256, gemm_smem>>>(X, WQ, WK, WV);
    attn_kernel<<<dim3(NSEQ / 64, HEADS), 256, attn_smem>>>(mask);
    proj_kernel<<<dim3(NSEQ / 128, FOUT / 64), 256, gemm_smem>>>(WO, out);
}

// round 15
// speedup vs baseline: 3.2186x; 1.2365x over previous
#include <cuda_runtime.h>
#include <cstdint>

#define HEADS 8
#define NSEQ  4096
#define FIN   512
#define HD    64
#define FOUT  512
#define NEG_INF -1e30f

// Scratch (allocation-free rule: __device__ globals).
__device__ uint32_t g_qh[HEADS * NSEQ * 32];          // Q pair-packed f16x2
__device__ uint32_t g_kh[HEADS * NSEQ * 32];          // K pair-packed f16x2
__device__ uint32_t g_vp[HEADS * (NSEQ / 2) * 64];    // V key-pair f16x2
__device__ uint32_t g_hcat[NSEQ * 256];               // hcat pair-packed f16x2

__device__ __forceinline__ uint32_t pack_f16(float lo, float hi) {
    uint32_t r;
    asm("cvt.rn.f16x2.f32 %0, %1, %2;" : "=r"(r) : "f"(hi), "f"(lo));
    return r;
}

__device__ __forceinline__ void mma_f16(float c[4],
    uint32_t a0, uint32_t a1, uint32_t a2, uint32_t a3,
    uint32_t b0, uint32_t b1)
{
    asm volatile(
        "mma.sync.aligned.m16n8k16.row.col.f32.f16.f16.f32 "
        "{%0,%1,%2,%3}, {%4,%5,%6,%7}, {%8,%9}, {%0,%1,%2,%3};"
        : "+f"(c[0]), "+f"(c[1]), "+f"(c[2]), "+f"(c[3])
        : "r"(a0), "r"(a1), "r"(a2), "r"(a3), "r"(b0), "r"(b1));
}

__device__ __forceinline__ int ppos(int w) {
    return (w >> 3) * 8 + ((w & 3) << 1) + ((w >> 2) & 1);
}

#define HP 40
#define VP 72

// ===========================================================================
// Kernel 1: QKV projection (unchanged from R13).
// ===========================================================================
__global__ void __launch_bounds__(256) qkv_kernel(
    const float* __restrict__ X,
    const float* __restrict__ WQ,
    const float* __restrict__ WK,
    const float* __restrict__ WV)
{
    extern __shared__ uint32_t smg[];
    uint32_t* As = smg;
    uint32_t* Bs = smg + 128 * HP;

    const int head  = blockIdx.z;
    const int which = blockIdx.y;
    const int m0    = blockIdx.x * 128;
    const float* A = X + (size_t)head * NSEQ * FIN + (size_t)m0 * FIN;
    const float* W = (which == 0 ? WQ : which == 1 ? WK : WV) + (size_t)head * HD * FIN;

    const int tid  = threadIdx.x;
    const int warp = tid >> 5;
    const int lane = tid & 31;
    const int wm   = warp >> 1;
    const int wn   = warp & 1;
    const int gr   = lane >> 2;
    const int gc   = lane & 3;

    float acc[2][4][4];
    #pragma unroll
    for (int i = 0; i < 2; i++)
        #pragma unroll
        for (int c = 0; c < 4; c++)
            #pragma unroll
            for (int j = 0; j < 4; j++) acc[i][c][j] = 0.0f;

    const int r   = tid >> 4;
    const int c4i = tid & 15;
    const int p0  = ppos(2 * c4i), p1 = ppos(2 * c4i + 1);

    for (int k0 = 0; k0 < FIN; k0 += 64) {
        #pragma unroll
        for (int rr = 0; rr < 8; rr++) {
            float4 v = *(const float4*)(A + (size_t)(r + rr * 16) * FIN + k0 + c4i * 4);
            uint32_t* p = As + (r + rr * 16) * HP;
            p[p0] = pack_f16(v.x, v.y);
            p[p1] = pack_f16(v.z, v.w);
        }
        #pragma unroll
        for (int rr = 0; rr < 4; rr++) {
            float4 v = *(const float4*)(W + (size_t)(r + rr * 16) * FIN + k0 + c4i * 4);
            uint32_t* p = Bs + (r + rr * 16) * HP;
            p[p0] = pack_f16(v.x, v.y);
            p[p1] = pack_f16(v.z, v.w);
        }
        __syncthreads();

        #pragma unroll
        for (int s = 0; s < 4; s++) {
            uint2 a[2][2];
            #pragma unroll
            for (int i = 0; i < 2; i++) {
                a[i][0] = *(const uint2*)&As[(wm * 32 + i * 16 + gr) * HP + s * 8 + 2 * gc];
                a[i][1] = *(const uint2*)&As[(wm * 32 + i * 16 + 8 + gr) * HP + s * 8 + 2 * gc];
            }
            #pragma unroll
            for (int c = 0; c < 4; c++) {
                uint2 b = *(const uint2*)&Bs[(wn * 32 + c * 8 + gr) * HP + s * 8 + 2 * gc];
                #pragma unroll
                for (int i = 0; i < 2; i++)
                    mma_f16(acc[i][c], a[i][0].x, a[i][1].x, a[i][0].y, a[i][1].y, b.x, b.y);
            }
        }
        __syncthreads();
    }

    if (which < 2) {
        uint32_t* out = (which == 0 ? g_qh : g_kh) + (size_t)head * NSEQ * 32;
        #pragma unroll
        for (int i = 0; i < 2; i++)
            #pragma unroll
            for (int c = 0; c < 4; c++) {
                const int row = m0 + wm * 32 + i * 16 + gr;
                const int p   = ppos(wn * 16 + c * 4 + gc);
                out[(size_t)row * 32 + p]       = pack_f16(acc[i][c][0], acc[i][c][1]);
                out[(size_t)(row + 8) * 32 + p] = pack_f16(acc[i][c][2], acc[i][c][3]);
            }
    } else {
        uint32_t* out = g_vp + (size_t)head * (NSEQ / 2) * 64;
        #pragma unroll
        for (int i = 0; i < 2; i++)
            #pragma unroll
            for (int c = 0; c < 4; c++) {
                const float t0 = __shfl_xor_sync(0xFFFFFFFFu, acc[i][c][0], 4);
                const float t1 = __shfl_xor_sync(0xFFFFFFFFu, acc[i][c][1], 4);
                const float t2 = __shfl_xor_sync(0xFFFFFFFFu, acc[i][c][2], 4);
                const float t3 = __shfl_xor_sync(0xFFFFFFFFu, acc[i][c][3], 4);
                const int base = m0 + wm * 32 + i * 16;
                const int n0   = wn * 32 + c * 8 + gc * 2;
                if (!(gr & 1)) {
                    const int pe = (base + gr) >> 1;
                    out[(size_t)pe * 64 + n0]     = pack_f16(acc[i][c][0], t0);
                    out[(size_t)pe * 64 + n0 + 1] = pack_f16(acc[i][c][1], t1);
                } else {
                    const int po = (base + 8 + gr - 1) >> 1;
                    out[(size_t)po * 64 + n0]     = pack_f16(t2, acc[i][c][2]);
                    out[(size_t)po * 64 + n0 + 1] = pack_f16(t3, acc[i][c][3]);
                }
            }
    }
}

// ===========================================================================
// Kernel 3: output projection (unchanged from R13).
// ===========================================================================
__global__ void __launch_bounds__(256) proj_kernel(
    const float* __restrict__ WO, float* __restrict__ out)
{
    extern __shared__ uint32_t smg[];
    uint32_t* As = smg;
    uint32_t* Bs = smg + 128 * HP;

    const int m0  = blockIdx.x * 128;
    const int n0  = blockIdx.y * 64;
    const float* B = WO + (size_t)n0 * (HEADS * HD);

    const int tid  = threadIdx.x;
    const int warp = tid >> 5;
    const int lane = tid & 31;
    const int wm   = warp >> 1;
    const int wn   = warp & 1;
    const int gr   = lane >> 2;
    const int gc   = lane & 3;

    float acc[2][4][4];
    #pragma unroll
    for (int i = 0; i < 2; i++)
        #pragma unroll
        for (int c = 0; c < 4; c++)
            #pragma unroll
            for (int j = 0; j < 4; j++) acc[i][c][j] = 0.0f;

    const int rh  = tid >> 1;
    const int hh  = tid & 1;
    const int r   = tid >> 4;
    const int c4i = tid & 15;
    const int p0  = ppos(2 * c4i), p1 = ppos(2 * c4i + 1);

    for (int k0 = 0; k0 < HEADS * HD; k0 += 64) {
        const int k0w = k0 >> 1;
        #pragma unroll
        for (int q = 0; q < 4; q++) {
            const int o = hh * 16 + q * 4;
            *(uint4*)&As[rh * HP + o] =
                *(const uint4*)(g_hcat + (size_t)(m0 + rh) * 256 + k0w + o);
        }
        #pragma unroll
        for (int rr = 0; rr < 4; rr++) {
            float4 v = *(const float4*)(B + (size_t)(r + rr * 16) * (HEADS * HD) + k0 + c4i * 4);
            uint32_t* p = Bs + (r + rr * 16) * HP;
            p[p0] = pack_f16(v.x, v.y);
            p[p1] = pack_f16(v.z, v.w);
        }
        __syncthreads();

        #pragma unroll
        for (int s = 0; s < 4; s++) {
            uint2 a[2][2];
            #pragma unroll
            for (int i = 0; i < 2; i++) {
                a[i][0] = *(const uint2*)&As[(wm * 32 + i * 16 + gr) * HP + s * 8 + 2 * gc];
                a[i][1] = *(const uint2*)&As[(wm * 32 + i * 16 + 8 + gr) * HP + s * 8 + 2 * gc];
            }
            #pragma unroll
            for (int c = 0; c < 4; c++) {
                uint2 b = *(const uint2*)&Bs[(wn * 32 + c * 8 + gr) * HP + s * 8 + 2 * gc];
                #pragma unroll
                for (int i = 0; i < 2; i++)
                    mma_f16(acc[i][c], a[i][0].x, a[i][1].x, a[i][0].y, a[i][1].y, b.x, b.y);
            }
        }
        __syncthreads();
    }

    #pragma unroll
    for (int i = 0; i < 2; i++)
        #pragma unroll
        for (int c = 0; c < 4; c++) {
            const int row = m0 + wm * 32 + i * 16 + gr;
            const int col = n0 + wn * 32 + c * 8 + gc * 2;
            *(float2*)&out[(size_t)row * FOUT + col]       = make_float2(acc[i][c][0], acc[i][c][1]);
            *(float2*)&out[(size_t)(row + 8) * FOUT + col] = make_float2(acc[i][c][2], acc[i][c][3]);
        }
}

// ===========================================================================
// Kernel 2: flash-attention v7.
//  - per-warp independent online softmax (no pmax exchange, no sync3)
//  - double-buffered K/V smem + register-staged LDG prefetch + mask prefetch
//  - ONE __syncthreads per iteration
// ===========================================================================
#define KBUF (64 * HP)   // 2560 words
#define VBUF (32 * VP)   // 2304 words

__global__ void __launch_bounds__(256) attn_kernel(const int* __restrict__ mask)
{
    extern __shared__ uint32_t sm[];
    // [0 .. 2*KBUF) : K double buffer ; [2*KBUF .. 2*KBUF+2*VBUF) : V double buffer
    uint32_t* KsBuf = sm;
    uint32_t* VsBuf = sm + 2 * KBUF;

    const int head = blockIdx.y;
    const int q0   = blockIdx.x * 64;
    const int tid  = threadIdx.x;
    const int warp = tid >> 5;
    const int lane = tid & 31;
    const int wm   = warp >> 1;
    const int wn   = warp & 1;
    const int gr   = lane >> 2;
    const int gc   = lane & 3;

    const uint32_t* Qg = g_qh + (size_t)head * NSEQ * 32;
    const uint32_t* Kg = g_kh + (size_t)head * NSEQ * 32;
    const uint32_t* Vg = g_vp + (size_t)head * (NSEQ / 2) * 64;
    const int*      M  = mask + (size_t)head * NSEQ * NSEQ;

    const int r4 = tid >> 2;
    const int qd = tid & 3;
    const int oA = (qd + 2 * (r4 & 1)) * 4;
    const int oB = oA ^ 16;
    const int pr = tid >> 3;
    const int oV = (tid & 7) * 4;

    const int r0 = wm * 16 + gr;
    const int r1 = r0 + 8;

    // ---- Q preamble: stage in buffer 0, hoist fragments ----
    {
        const uint32_t* src = Qg + (size_t)(q0 + r4) * 32;
        *(uint4*)&KsBuf[r4 * HP + oA] = *(const uint4*)(src + oA);
        *(uint4*)&KsBuf[r4 * HP + oB] = *(const uint4*)(src + oB);
    }
    __syncthreads();
    uint2 qa[4], qb[4];
    #pragma unroll
    for (int s = 0; s < 4; s++) {
        qa[s] = *(const uint2*)&KsBuf[r0 * HP + s * 8 + 2 * gc];
        qb[s] = *(const uint2*)&KsBuf[r1 * HP + s * 8 + 2 * gc];
    }
    __syncthreads();   // all warps done reading Q staging before iter0 STS

    // ---- preload tile 0 into registers ----
    uint4 stK0, stK1, stV0, stV1;
    int2  mk[4][2];
    {
        const uint32_t* srcK = Kg + (size_t)r4 * 32;
        stK0 = *(const uint4*)(srcK + oA);
        stK1 = *(const uint4*)(srcK + oB);
        const uint32_t* srcV = Vg + (size_t)pr * 64;
        stV0 = *(const uint4*)(srcV + oV);
        stV1 = *(const uint4*)(srcV + oV + 32);
        #pragma unroll
        for (int c = 0; c < 4; c++) {
            const int col = wn * 32 + c * 8 + gc * 2;
            mk[c][0] = *(const int2*)(M + (size_t)(q0 + r0) * NSEQ + col);
            mk[c][1] = *(const int2*)(M + (size_t)(q0 + r1) * NSEQ + col);
        }
    }

    // per-warp partial state
    float m0 = -3e38f, m1 = -3e38f;
    float l0 = 0.0f,  l1 = 0.0f;
    float o[8][4];
    #pragma unroll
    for (int c = 0; c < 8; c++)
        #pragma unroll
        for (int j = 0; j < 4; j++) o[c][j] = 0.0f;

    for (int kt = 0; kt < NSEQ / 64; kt++) {
        uint32_t* Ks = KsBuf + (kt & 1) * KBUF;
        uint32_t* Vs = VsBuf + (kt & 1) * VBUF;

        // publish staged tile kt
        *(uint4*)&Ks[r4 * HP + oA] = stK0;
        *(uint4*)&Ks[r4 * HP + oB] = stK1;
        *(uint4*)&Vs[pr * VP + oV]      = stV0;
        *(uint4*)&Vs[pr * VP + oV + 32] = stV1;

        // prefetch tile kt+1 (K/V + mask) into registers
        int2 mkn[4][2];
        if (kt + 1 < NSEQ / 64) {
            const int kn = (kt + 1) * 64;
            const uint32_t* srcK = Kg + (size_t)(kn + r4) * 32;
            stK0 = *(const uint4*)(srcK + oA);
            stK1 = *(const uint4*)(srcK + oB);
            const uint32_t* srcV = Vg + (size_t)((kn >> 1) + pr) * 64;
            stV0 = *(const uint4*)(srcV + oV);
            stV1 = *(const uint4*)(srcV + oV + 32);
            #pragma unroll
            for (int c = 0; c < 4; c++) {
                const int col = kn + wn * 32 + c * 8 + gc * 2;
                mkn[c][0] = *(const int2*)(M + (size_t)(q0 + r0) * NSEQ + col);
                mkn[c][1] = *(const int2*)(M + (size_t)(q0 + r1) * NSEQ + col);
            }
        }

        __syncthreads();  // the ONE barrier: publishes tile kt, protects buffers

        // ---- S = Q K^T ----
        float sc[4][4];
        #pragma unroll
        for (int c = 0; c < 4; c++)
            #pragma unroll
            for (int j = 0; j < 4; j++) sc[c][j] = 0.0f;

        #pragma unroll
        for (int s = 0; s < 4; s++) {
            #pragma unroll
            for (int c = 0; c < 4; c++) {
                const uint2 b = *(const uint2*)&Ks[(wn * 32 + c * 8 + gr) * HP + s * 8 + 2 * gc];
                mma_f16(sc[c], qa[s].x, qb[s].x, qa[s].y, qb[s].y, b.x, b.y);
            }
        }

        // ---- scale + mask ----
        #pragma unroll
        for (int c = 0; c < 4; c++) {
            sc[c][0] = mk[c][0].x ? sc[c][0] * 0.125f : NEG_INF;
            sc[c][1] = mk[c][0].y ? sc[c][1] * 0.125f : NEG_INF;
            sc[c][2] = mk[c][1].x ? sc[c][2] * 0.125f : NEG_INF;
            sc[c][3] = mk[c][1].y ? sc[c][3] * 0.125f : NEG_INF;
        }
        // rotate mask prefetch
        #pragma unroll
        for (int c = 0; c < 4; c++) { mk[c][0] = mkn[c][0]; mk[c][1] = mkn[c][1]; }

        // ---- per-warp row max (own 32-key slice only) ----
        float rm0 = -3e38f, rm1 = -3e38f;
        #pragma unroll
        for (int c = 0; c < 4; c++) {
            rm0 = fmaxf(rm0, fmaxf(sc[c][0], sc[c][1]));
            rm1 = fmaxf(rm1, fmaxf(sc[c][2], sc[c][3]));
        }
        rm0 = fmaxf(rm0, __shfl_xor_sync(0xFFFFFFFFu, rm0, 1));
        rm0 = fmaxf(rm0, __shfl_xor_sync(0xFFFFFFFFu, rm0, 2));
        rm1 = fmaxf(rm1, __shfl_xor_sync(0xFFFFFFFFu, rm1, 1));
        rm1 = fmaxf(rm1, __shfl_xor_sync(0xFFFFFFFFu, rm1, 2));

        const float mn0 = fmaxf(m0, rm0);
        const float mn1 = fmaxf(m1, rm1);
        const float al0 = __expf(m0 - mn0);
        const float al1 = __expf(m1 - mn1);
        m0 = mn0; m1 = mn1;

        // ---- exp, partial sums ----
        float rs0 = 0.0f, rs1 = 0.0f;
        #pragma unroll
        for (int c = 0; c < 4; c++) {
            sc[c][0] = __expf(sc[c][0] - mn0);
            sc[c][1] = __expf(sc[c][1] - mn0);
            sc[c][2] = __expf(sc[c][2] - mn1);
            sc[c][3] = __expf(sc[c][3] - mn1);
            rs0 += sc[c][0] + sc[c][1];
            rs1 += sc[c][2] + sc[c][3];
        }
        rs0 += __shfl_xor_sync(0xFFFFFFFFu, rs0, 1);
        rs0 += __shfl_xor_sync(0xFFFFFFFFu, rs0, 2);
        rs1 += __shfl_xor_sync(0xFFFFFFFFu, rs1, 1);
        rs1 += __shfl_xor_sync(0xFFFFFFFFu, rs1, 2);
        l0 = l0 * al0 + rs0;
        l1 = l1 * al1 + rs1;

        // ---- O rescale + O += P V ----
        #pragma unroll
        for (int c = 0; c < 8; c++) {
            o[c][0] *= al0; o[c][1] *= al0;
            o[c][2] *= al1; o[c][3] *= al1;
        }
        #pragma unroll
        for (int s = 0; s < 2; s++) {
            const uint32_t a0 = pack_f16(sc[2*s][0],   sc[2*s][1]);
            const uint32_t a1 = pack_f16(sc[2*s][2],   sc[2*s][3]);
            const uint32_t a2 = pack_f16(sc[2*s+1][0], sc[2*s+1][1]);
            const uint32_t a3 = pack_f16(sc[2*s+1][2], sc[2*s+1][3]);
            const int kpb = wn * 16 + s * 8 + gc;
            #pragma unroll
            for (int c = 0; c < 8; c++) {
                const int d = c * 8 + gr;
                const uint32_t b0 = Vs[kpb * VP + d];
                const uint32_t b1 = Vs[(kpb + 4) * VP + d];
                mma_f16(o[c], a0, a1, a2, a3, b0, b1);
            }
        }
    }
    __syncthreads();  // loop done; smem free for combine

    // ---- cross-warp combine with per-warp m: O = Σ O_w e^{m_w−m}, l likewise ----
    float* Os = (float*)sm;          // [64][65]
    float* Ls = Os + 64 * 65;        // [64]
    float* Ms = Ls + 64;             // [64]
    if (wn == 1) {
        #pragma unroll
        for (int c = 0; c < 8; c++) {
            const int d = c * 8 + gc * 2;
            Os[r0 * 65 + d] = o[c][0]; Os[r0 * 65 + d + 1] = o[c][1];
            Os[r1 * 65 + d] = o[c][2]; Os[r1 * 65 + d + 1] = o[c][3];
        }
        if (gc == 0) { Ls[r0] = l0; Ls[r1] = l1; Ms[r0] = m0; Ms[r1] = m1; }
    }
    __syncthreads();
    if (wn == 0) {
        const float mm0 = fmaxf(m0, Ms[r0]);
        const float mm1 = fmaxf(m1, Ms[r1]);
        const float ea0 = __expf(m0 - mm0), eb0 = __expf(Ms[r0] - mm0);
        const float ea1 = __expf(m1 - mm1), eb1 = __expf(Ms[r1] - mm1);
        const float inv0 = 1.0f / (l0 * ea0 + Ls[r0] * eb0);
        const float inv1 = 1.0f / (l1 * ea1 + Ls[r1] * eb1);
        #pragma unroll
        for (int c = 0; c < 8; c++) {
            const int dl = c * 8 + gc * 2;
            const int p  = ppos(head * 32 + c * 4 + gc);
            g_hcat[(size_t)(q0 + r0) * 256 + p] =
                pack_f16((o[c][0] * ea0 + Os[r0 * 65 + dl]     * eb0) * inv0,
                         (o[c][1] * ea0 + Os[r0 * 65 + dl + 1] * eb0) * inv0);
            g_hcat[(size_t)(q0 + r1) * 256 + p] =
                pack_f16((o[c][2] * ea1 + Os[r1 * 65 + dl]     * eb1) * inv1,
                         (o[c][3] * ea1 + Os[r1 * 65 + dl + 1] * eb1) * inv1);
        }
    }
}

// ---------------------------------------------------------------------------
extern "C" void kernel_launch(void* const* d_in, const int* in_sizes, int n_in,
                              void* d_out, int out_size)
{
    const float* X    = (const float*)d_in[0];
    const int*   mask = (const int*)  d_in[1];
    const float* WQ   = (const float*)d_in[2];
    const float* WK   = (const float*)d_in[3];
    const float* WV   = (const float*)d_in[4];
    const float* WO   = (const float*)d_in[5];
    float* out = (float*)d_out;

    const int gemm_smem = (128 + 64) * HP * 4;            // 30720 B
    const int attn_smem = (2 * KBUF + 2 * VBUF) * 4;      // 38912 B

    static int configured = 0;
    if (!configured) {
        cudaFuncSetAttribute(qkv_kernel,  cudaFuncAttributeMaxDynamicSharedMemorySize, gemm_smem);
        cudaFuncSetAttribute(proj_kernel, cudaFuncAttributeMaxDynamicSharedMemorySize, gemm_smem);
        cudaFuncSetAttribute(attn_kernel, cudaFuncAttributeMaxDynamicSharedMemorySize, attn_smem);
        configured = 1;
    }

    qkv_kernel<<<dim3(NSEQ / 128, 3, HEADS), 256, gemm_smem>>>(X, WQ, WK, WV);
    attn_kernel<<<dim3(NSEQ / 64, HEADS), 256, attn_smem>>>(mask);
    proj_kernel<<<dim3(NSEQ / 128, FOUT / 64), 256, gemm_smem>>>(WO, out);
}